// round 2
// baseline (speedup 1.0000x reference)
#include <cuda_runtime.h>
#include <math.h>

#define PI_F 3.14159265358979323846f

// ---------------- static device scratch ----------------
__device__ float2 g_tw[65536];              // e^{-2*pi*i*t/65536}
__device__ float  g_routed[256 * 128];
__device__ float  g_dw[8 * 4 * 128];
__device__ float  g_invnorm[128];
__device__ float  g_frames[128 * 32 * 2048];
__device__ float  g_res[128 * 32768];
__device__ float2 g_Fsig[16777216];         // 256 x 65536
__device__ float2 g_Fres[8388608];          // 128 x 65536
__device__ float2 g_B[33554432];            // 512 x 65536
__device__ float  g_conv[33554432];         // 1024 x 32768

__device__ __forceinline__ float2 cmul(float2 a, float2 b) {
  return make_float2(a.x * b.x - a.y * b.y, a.x * b.y + a.y * b.x);
}
__device__ __forceinline__ unsigned rotl32(unsigned x, int r) {
  return (x << r) | (x >> (32 - r));
}

// JAX threefry2x32, partitionable 32-bit path: key=(0,123), count hi=0, lo=idx,
// bits = out0 ^ out1 -> uniform [-1,1).
__device__ __forceinline__ float noise_pm1(unsigned idx) {
  const unsigned ks0 = 0u, ks1 = 123u;
  const unsigned ks2 = ks0 ^ ks1 ^ 0x1BD11BDAu;
  unsigned x0 = ks0;
  unsigned x1 = idx + ks1;
#define TFR(r) { x0 += x1; x1 = rotl32(x1, r); x1 ^= x0; }
  TFR(13) TFR(15) TFR(26) TFR(6)
  x0 += ks1; x1 += ks2 + 1u;
  TFR(17) TFR(29) TFR(16) TFR(24)
  x0 += ks2; x1 += ks0 + 2u;
  TFR(13) TFR(15) TFR(26) TFR(6)
  x0 += ks0; x1 += ks1 + 3u;
  TFR(17) TFR(29) TFR(16) TFR(24)
  x0 += ks1; x1 += ks2 + 4u;
  TFR(13) TFR(15) TFR(26) TFR(6)
  x0 += ks2; x1 += ks0 + 5u;
#undef TFR
  unsigned bits = x0 ^ x1;
  float f = __uint_as_float((bits >> 9) | 0x3f800000u) - 1.0f;
  return f * 2.0f - 1.0f;
}

// radix-2 DIT FFT-256 in smem, input already bit-reversed. j in [0,128).
template <int FIRST>
__device__ __forceinline__ void fft256s(float2* S, int j, const float2* T) {
#pragma unroll
  for (int ls = FIRST; ls <= 8; ls++) {
    int half = 1 << (ls - 1);
    int off  = j & (half - 1);
    int i0   = ((j >> (ls - 1)) << ls) + off;
    int i1   = i0 + half;
    float2 w = T[off << (8 - ls)];
    float2 a = S[i0], b = S[i1];
    float2 t = cmul(w, b);
    S[i0] = make_float2(a.x + t.x, a.y + t.y);
    S[i1] = make_float2(a.x - t.x, a.y - t.y);
    __syncthreads();
  }
}

// ---------------- K0: twiddle table ----------------
__global__ void k_tw() {
  int t = blockIdx.x * 256 + threadIdx.x;
  float s, c;
  sincospif((float)t * (-1.0f / 32768.0f), &s, &c);
  g_tw[t] = make_float2(c, s);
}

// ---------------- K1: routing einsum + before_upsample ----------------
__global__ void __launch_bounds__(256) k_routed(const float* __restrict__ cs,
                                                const float* __restrict__ router,
                                                float* __restrict__ out) {
  int i = blockIdx.x * 256 + threadIdx.x;  // 32768 = 8bc * 32r * 128f
  int f = i & 127, r = (i >> 7) & 31, bc = i >> 12;
  float acc = 0.0f;
#pragma unroll
  for (int c = 0; c < 16; c++)
    acc += cs[(bc * 16 + c) * 128 + f] * router[c * 32 + r];
  g_routed[i] = acc;
  out[262144 + i] = acc;  // before_upsample
}

// ---------------- K1b: deformation softmax ----------------
__global__ void __launch_bounds__(256) k_dw(const float* __restrict__ defs) {
  int i = blockIdx.x * 256 + threadIdx.x;  // 1024 = 8bc*128f
  if (i >= 1024) return;
  int f = i & 127, bc = i >> 7;
  float v[4], mx = -1e30f;
#pragma unroll
  for (int e = 0; e < 4; e++) {
    float x = defs[(bc * 4 + e) * 128 + f] + (e == 0 ? 1.0f : 0.0f);
    v[e] = x; mx = fmaxf(mx, x);
  }
  float s = 0.0f;
#pragma unroll
  for (int e = 0; e < 4; e++) { v[e] = expf(v[e] - mx); s += v[e]; }
  float inv = 1.0f / s;
#pragma unroll
  for (int e = 0; e < 4; e++) g_dw[bc * 512 + e * 128 + f] = v[e] * inv;
}

// ---------------- K2: per-frame irfft(2048) * hann ----------------
__global__ void __launch_bounds__(1024) k_frames(const float* __restrict__ amp,
                                                 const float* __restrict__ phase,
                                                 const float* __restrict__ decay) {
  __shared__ float2 S[2048];
  __shared__ float2 T2[1024];
  const int tid = threadIdx.x;
  const int f = blockIdx.x, re = blockIdx.y;
  const int r = re >> 2, e = re & 3;
  {
    float2 w = g_tw[tid * 32];
    T2[tid] = make_float2(w.x, -w.y);  // inverse sign
  }
  const float fp1 = (float)(f + 1);
#pragma unroll
  for (int h = 0; h < 2; h++) {
    int n = tid + h * 1024;
    int k = (n <= 1024) ? n : (2048 - n);
    int base = (r * 1025 + k) * 4 + e;
    float av = fabsf(amp[base]);
    float dc = 0.5f + 0.45f / (1.0f + expf(-decay[base]));
    float mag = av * expf(fp1 * logf(dc + 1e-12f));
    float ph = tanhf(phase[base]) * PI_F;
    float sv, cv; sincosf(ph, &sv, &cv);
    float im = mag * sv;
    if (n > 1024) im = -im;
    S[__brev((unsigned)n) >> 21] = make_float2(mag * cv, im);
  }
  __syncthreads();
#pragma unroll
  for (int ls = 1; ls <= 11; ls++) {
    int half = 1 << (ls - 1);
    int off  = tid & (half - 1);
    int i0   = ((tid >> (ls - 1)) << ls) + off;
    int i1   = i0 + half;
    float2 w = T2[off << (11 - ls)];
    float2 a = S[i0], b = S[i1];
    float2 t = cmul(w, b);
    S[i0] = make_float2(a.x + t.x, a.y + t.y);
    S[i1] = make_float2(a.x - t.x, a.y - t.y);
    __syncthreads();
  }
  float* dst = g_frames + ((size_t)re * 32 + f) * 2048;
#pragma unroll
  for (int h = 0; h < 2; h++) {
    int t = tid + h * 1024;
    float hann = 0.5f - 0.5f * g_tw[(t * 32) & 65535].x;
    dst[t] = S[t].x * (hann * (1.0f / 2048.0f));
  }
}

// ---------------- K3: overlap-add + inv-norm ----------------
__global__ void __launch_bounds__(1024) k_oa() {
  const int re = blockIdx.x, tid = threadIdx.x;
  const float* F = g_frames + (size_t)re * 32 * 2048;
  float* R = g_res + (size_t)re * 32768;
  float ss = 0.0f;
#pragma unroll
  for (int f = 0; f < 32; f++) {
    float v = F[f * 2048 + tid];
    if (f > 0) v += F[(f - 1) * 2048 + 1024 + tid];
    R[f * 1024 + tid] = v;
    ss += v * v;
  }
#pragma unroll
  for (int o = 16; o > 0; o >>= 1) ss += __shfl_xor_sync(0xffffffffu, ss, o);
  __shared__ float red[32];
  if ((tid & 31) == 0) red[tid >> 5] = ss;
  __syncthreads();
  if (tid < 32) {
    float v = red[tid];
#pragma unroll
    for (int o = 16; o > 0; o >>= 1) v += __shfl_xor_sync(0xffffffffu, v, o);
    if (tid == 0) g_invnorm[re] = 1.0f / (sqrtf(v) + 1e-8f);
  }
}

// ---------------- K4: forward pass1 (signals), fused upsample*noise ----------------
__global__ void __launch_bounds__(1024) k_fwd_sig_p1() {
  __shared__ float2 S[8 * 258];
  __shared__ float2 Tf[128];
  __shared__ float  rrow[128];
  const int tid = threadIdx.x, c = tid >> 7, j = tid & 127;
  const int s = blockIdx.y, b = blockIdx.x * 8 + c;
  if (tid < 128) { Tf[tid] = g_tw[tid * 256]; rrow[tid] = g_routed[s * 128 + tid]; }
  __syncthreads();
  int n = b + 256 * j;  // < 32768 always
  float pos = fminf(fmaxf((n + 0.5f) * (1.0f / 256.0f) - 0.5f, 0.0f), 127.0f);
  int lo = (int)pos;
  int hi = min(lo + 1, 127);
  float w = pos - (float)lo;
  float v = (rrow[lo] * (1.0f - w) + rrow[hi] * w) * noise_pm1((unsigned)(s * 32768 + n));
  float2* Sc = S + c * 258;
  int p = __brev((unsigned)j) >> 24;
  Sc[p] = make_float2(v, 0.0f);
  Sc[p + 1] = make_float2(v, 0.0f);  // stage-1 result (upper half zero-padded)
  __syncthreads();
  fft256s<2>(Sc, j, Tf);
#pragma unroll
  for (int h = 0; h < 2; h++) {  // twiddle + transposed (coalesced) store
    int o = tid + h * 1024;
    int dd = o >> 3, bl = o & 7;
    float2 z = S[bl * 258 + dd];
    int bg = blockIdx.x * 8 + bl;
    float2 tw = g_tw[(dd * bg) & 65535];
    g_Fsig[s * 65536 + dd * 256 + bg] = cmul(z, tw);
  }
}

// ---------------- K5: forward pass1 (resonances, unit-normed) ----------------
__global__ void __launch_bounds__(1024) k_fwd_res_p1() {
  __shared__ float2 S[8 * 258];
  __shared__ float2 Tf[128];
  const int tid = threadIdx.x, c = tid >> 7, j = tid & 127;
  const int re = blockIdx.y, b = blockIdx.x * 8 + c;
  if (tid < 128) Tf[tid] = g_tw[tid * 256];
  __syncthreads();
  float v = g_res[re * 32768 + b + 256 * j] * g_invnorm[re];
  float2* Sc = S + c * 258;
  int p = __brev((unsigned)j) >> 24;
  Sc[p] = make_float2(v, 0.0f);
  Sc[p + 1] = make_float2(v, 0.0f);
  __syncthreads();
  fft256s<2>(Sc, j, Tf);
#pragma unroll
  for (int h = 0; h < 2; h++) {
    int o = tid + h * 1024;
    int dd = o >> 3, bl = o & 7;
    float2 z = S[bl * 258 + dd];
    int bg = blockIdx.x * 8 + bl;
    float2 tw = g_tw[(dd * bg) & 65535];
    g_Fres[re * 65536 + dd * 256 + bg] = cmul(z, tw);
  }
}

// ---------------- K6: forward pass2 (in-place rows) ----------------
__global__ void __launch_bounds__(1024) k_fwd_p2(int which) {
  __shared__ float2 S[8 * 258];
  __shared__ float2 Tf[128];
  const int tid = threadIdx.x, c = tid >> 7, j = tid & 127;
  float2* buf = which ? g_Fres : g_Fsig;
  const int row = blockIdx.y, d = blockIdx.x * 8 + c;
  if (tid < 128) Tf[tid] = g_tw[tid * 256];
  __syncthreads();
  float2* src = buf + row * 65536 + d * 256;
  float2* Sc = S + c * 258;
  Sc[__brev((unsigned)j) >> 24]         = src[j];
  Sc[__brev((unsigned)(j + 128)) >> 24] = src[j + 128];
  __syncthreads();
  fft256s<1>(Sc, j, Tf);
  src[j] = Sc[j];
  src[j + 128] = Sc[j + 128];
}

// ---------------- K7: inverse pass1, fused product, packed pairs ----------------
__global__ void __launch_bounds__(1024) k_inv_p1() {
  __shared__ float2 S[8 * 258];
  __shared__ float2 Ti[128];
  const int tid = threadIdx.x, c = tid >> 7, j = tid & 127;
  const int pq = blockIdx.y;          // 512 packs
  const int sr = pq >> 1, hb = pq & 1;
  const int re0 = (sr & 31) * 4 + 2 * hb;
  const int k1 = blockIdx.x * 8 + c;
  if (tid < 128) { float2 w = g_tw[tid * 256]; Ti[tid] = make_float2(w.x, -w.y); }
  __syncthreads();
  const float2* fs = g_Fsig + sr * 65536 + k1 * 256;
  const float2* f0 = g_Fres + re0 * 65536 + k1 * 256;
  const float2* f1 = f0 + 65536;
  float2* Sc = S + c * 258;
#pragma unroll
  for (int h = 0; h < 2; h++) {
    int k2 = j + h * 128;
    float2 a = fs[k2];
    float2 p0 = cmul(a, f0[k2]);
    float2 p1 = cmul(a, f1[k2]);
    Sc[__brev((unsigned)k2) >> 24] = make_float2(p0.x - p1.y, p0.y + p1.x);
  }
  __syncthreads();
  fft256s<1>(Sc, j, Ti);
#pragma unroll
  for (int h = 0; h < 2; h++) {
    int o = tid + h * 1024;
    int cc = o >> 3, kl = o & 7;
    int kg = blockIdx.x * 8 + kl;
    float2 z = S[kl * 258 + cc];
    float2 w = g_tw[(kg * cc) & 65535];
    w.y = -w.y;  // conj: inverse twiddle
    g_B[pq * 65536 + cc * 256 + kg] = cmul(z, w);
  }
}

// ---------------- K8: inverse pass2, real/imag unpack to conv ----------------
__global__ void __launch_bounds__(1024) k_inv_p2() {
  __shared__ float2 S[8 * 258];
  __shared__ float2 Ti[128];
  const int tid = threadIdx.x, c = tid >> 7, j = tid & 127;
  const int pq = blockIdx.y, C0 = blockIdx.x * 8;
  if (tid < 128) { float2 w = g_tw[tid * 256]; Ti[tid] = make_float2(w.x, -w.y); }
  __syncthreads();
  const float2* src = g_B + pq * 65536 + (C0 + c) * 256;
  float2* Sc = S + c * 258;
  Sc[__brev((unsigned)j) >> 24]         = src[j];
  Sc[__brev((unsigned)(j + 128)) >> 24] = src[j + 128];
  __syncthreads();
  fft256s<1>(Sc, j, Ti);
  // keep only n = c + 256m < 32768 (m < 128): 8c x 128m = 1024 outputs
  int m = tid >> 3, cl = tid & 7;
  float2 z = S[cl * 258 + m];
  int sr = pq >> 1, hb = pq & 1;
  int q0 = sr * 4 + 2 * hb;
  int n = (C0 + cl) + 256 * m;
  g_conv[q0 * 32768 + n]       = z.x * (1.0f / 65536.0f);
  g_conv[(q0 + 1) * 32768 + n] = z.y * (1.0f / 65536.0f);
}

// ---------------- K9: deformation mix + tanh + sum over r ----------------
__global__ void __launch_bounds__(256) k_final(const float* __restrict__ gains,
                                               float* __restrict__ out) {
  __shared__ float dw[512];
  __shared__ float ga[32];
  const int tid = threadIdx.x, bc = blockIdx.y;
  for (int i = tid; i < 512; i += 256) dw[i] = g_dw[bc * 512 + i];
  if (tid < 32) ga[tid] = fabsf(gains[tid]);
  __syncthreads();
  int n = blockIdx.x * 256 + tid;
  float pos = fminf(fmaxf((n + 0.5f) * (1.0f / 256.0f) - 0.5f, 0.0f), 127.0f);
  int lo = (int)pos;
  int hi = min(lo + 1, 127);
  float w = pos - (float)lo;
  float d0 = dw[lo]       * (1.0f - w) + dw[hi]       * w;
  float d1 = dw[128 + lo] * (1.0f - w) + dw[128 + hi] * w;
  float d2 = dw[256 + lo] * (1.0f - w) + dw[256 + hi] * w;
  float d3 = dw[384 + lo] * (1.0f - w) + dw[384 + hi] * w;
  float acc = 0.0f;
  const float* cv = g_conv + bc * 32 * 4 * 32768 + n;
#pragma unroll 4
  for (int r = 0; r < 32; r++) {
    const float* p = cv + r * 4 * 32768;
    float sx = d0 * p[0] + d1 * p[32768] + d2 * p[65536] + d3 * p[98304];
    acc += tanhf(sx * ga[r]);
  }
  out[bc * 32768 + n] = acc;
}

extern "C" void kernel_launch(void* const* d_in, const int* in_sizes, int n_in,
                              void* d_out, int out_size) {
  const float* cs     = (const float*)d_in[0];
  const float* defs   = (const float*)d_in[1];
  const float* router = (const float*)d_in[2];
  const float* amp    = (const float*)d_in[3];
  const float* phase  = (const float*)d_in[4];
  const float* decay  = (const float*)d_in[5];
  const float* gains  = (const float*)d_in[6];
  float* out = (float*)d_out;

  k_tw<<<256, 256>>>();
  k_routed<<<128, 256>>>(cs, router, out);
  k_dw<<<4, 256>>>(defs);
  k_frames<<<dim3(32, 128), 1024>>>(amp, phase, decay);
  k_oa<<<128, 1024>>>();
  k_fwd_sig_p1<<<dim3(32, 256), 1024>>>();
  k_fwd_res_p1<<<dim3(32, 128), 1024>>>();
  k_fwd_p2<<<dim3(32, 256), 1024>>>(0);
  k_fwd_p2<<<dim3(32, 128), 1024>>>(1);
  k_inv_p1<<<dim3(32, 512), 1024>>>();
  k_inv_p2<<<dim3(32, 512), 1024>>>();
  k_final<<<dim3(128, 8), 256>>>(gains, out);
}

// round 3
// speedup vs baseline: 2.7733x; 2.7733x over previous
#include <cuda_runtime.h>
#include <math.h>

#define PI_F   3.14159265358979323846f
#define TWOPI_F 6.2831853071795864769f

// ---------------- static device scratch ----------------
__device__ float2 g_tw[65536];              // e^{-2*pi*i*t/65536} (used by k_frames)
__device__ float  g_routed[256 * 128];
__device__ float  g_dw[8 * 4 * 128];
__device__ float  g_invnorm[128];
__device__ float  g_frames[128 * 32 * 2048];
__device__ float  g_res[128 * 32768];
__device__ float2 g_Fsig[16777216];         // 256 x 65536  (pass1 output)
__device__ float2 g_Fres[8388608];          // 128 x 65536  (pass1 -> in-place pass2)
__device__ float2 g_B[33554432];            // 512 x 65536  (inverse pass1 output)
__device__ float2 g_conv2[16777216];        // 512 x 32768  packed conv pairs

__device__ __forceinline__ float2 cmul(float2 a, float2 b) {
  return make_float2(a.x * b.x - a.y * b.y, a.x * b.y + a.y * b.x);
}
__device__ __forceinline__ unsigned rotl32(unsigned x, int r) {
  return (x << r) | (x >> (32 - r));
}

// JAX threefry2x32, partitionable 32-bit path: key=(0,123), count hi=0, lo=idx,
// bits = out0 ^ out1 -> uniform [-1,1).
__device__ __forceinline__ float noise_pm1(unsigned idx) {
  const unsigned ks0 = 0u, ks1 = 123u;
  const unsigned ks2 = ks0 ^ ks1 ^ 0x1BD11BDAu;
  unsigned x0 = ks0;
  unsigned x1 = idx + ks1;
#define TFR(r) { x0 += x1; x1 = rotl32(x1, r); x1 ^= x0; }
  TFR(13) TFR(15) TFR(26) TFR(6)
  x0 += ks1; x1 += ks2 + 1u;
  TFR(17) TFR(29) TFR(16) TFR(24)
  x0 += ks2; x1 += ks0 + 2u;
  TFR(13) TFR(15) TFR(26) TFR(6)
  x0 += ks0; x1 += ks1 + 3u;
  TFR(17) TFR(29) TFR(16) TFR(24)
  x0 += ks1; x1 += ks2 + 4u;
  TFR(13) TFR(15) TFR(26) TFR(6)
  x0 += ks2; x1 += ks0 + 5u;
#undef TFR
  unsigned bits = x0 ^ x1;
  float f = __uint_as_float((bits >> 9) | 0x3f800000u) - 1.0f;
  return f * 2.0f - 1.0f;
}

// ---------------- register DFT-16 (input bit-reversed, output natural) ----------------
// S = -1 forward (e^{-i}), S = +1 inverse (e^{+i}).
template <int S>
__device__ __forceinline__ void fft16r(float2* r) {
  const float C1 = 0.9238795325112867f, S1 = 0.3826834323650898f, R2 = 0.7071067811865476f;
  const float sg = (float)S;
#define BF0(i0,i1) { float ax=r[i0].x, ay=r[i0].y, bx=r[i1].x, by=r[i1].y; \
  r[i0]=make_float2(ax+bx,ay+by); r[i1]=make_float2(ax-bx,ay-by); }
#define BFI(i0,i1) { float ax=r[i0].x, ay=r[i0].y, bx=r[i1].x, by=r[i1].y; \
  float tx=-sg*by, ty=sg*bx; \
  r[i0]=make_float2(ax+tx,ay+ty); r[i1]=make_float2(ax-tx,ay-ty); }
#define BFW(i0,i1,wr,wi) { float ax=r[i0].x, ay=r[i0].y, bx=r[i1].x, by=r[i1].y; \
  float tx=(wr)*bx-(wi)*by, ty=(wr)*by+(wi)*bx; \
  r[i0]=make_float2(ax+tx,ay+ty); r[i1]=make_float2(ax-tx,ay-ty); }
  // stage 1
  BF0(0,1) BF0(2,3) BF0(4,5) BF0(6,7) BF0(8,9) BF0(10,11) BF0(12,13) BF0(14,15)
  // stage 2
  BF0(0,2) BFI(1,3) BF0(4,6) BFI(5,7) BF0(8,10) BFI(9,11) BF0(12,14) BFI(13,15)
  // stage 3
  BF0(0,4) BFW(1,5, R2, sg*R2) BFI(2,6) BFW(3,7, -R2, sg*R2)
  BF0(8,12) BFW(9,13, R2, sg*R2) BFI(10,14) BFW(11,15, -R2, sg*R2)
  // stage 4
  BF0(0,8) BFW(1,9, C1, sg*S1) BFW(2,10, R2, sg*R2) BFW(3,11, S1, sg*C1)
  BFI(4,12) BFW(5,13, -S1, sg*C1) BFW(6,14, -R2, sg*R2) BFW(7,15, -C1, sg*S1)
#undef BF0
#undef BFI
#undef BFW
}

// FFT-256 on 16 threads x 16 regs. Input x[n2] = v[lane + 16*n2] (natural),
// output x[k2] = V[lane + 16*k2]. tileC: per-group smem, >= 16*17 float2.
// BS=true: group spans warps (block syncs); BS=false: group is 16 contiguous
// threads inside one warp (warp syncs).
template <int S, bool BS>
__device__ __forceinline__ void fft256g(float2* x, int lane, float2* tileC) {
  const int BR0=0,BR1=8,BR2=4,BR3=12,BR4=2,BR5=10,BR6=6,BR7=14,
            BR8=1,BR9=9,BR10=5,BR11=13,BR12=3,BR13=11,BR14=7,BR15=15;
  float2 q[16];
  q[0]=x[BR0]; q[1]=x[BR1]; q[2]=x[BR2]; q[3]=x[BR3];
  q[4]=x[BR4]; q[5]=x[BR5]; q[6]=x[BR6]; q[7]=x[BR7];
  q[8]=x[BR8]; q[9]=x[BR9]; q[10]=x[BR10]; q[11]=x[BR11];
  q[12]=x[BR12]; q[13]=x[BR13]; q[14]=x[BR14]; q[15]=x[BR15];
  fft16r<S>(q);
  // inter-stage twiddle e^{S*2pi*i*lane*k1/256} via recurrence
  float sv, cv;
  __sincosf((float)S * (TWOPI_F / 256.0f) * (float)lane, &sv, &cv);
  float2 stp = make_float2(cv, sv);
  float2 w = make_float2(1.0f, 0.0f);
  if (BS) __syncthreads(); else __syncwarp();
#pragma unroll
  for (int k1 = 0; k1 < 16; k1++) {
    tileC[k1 * 17 + lane] = cmul(q[k1], w);
    w = cmul(w, stp);
  }
  if (BS) __syncthreads(); else __syncwarp();
  q[0]=tileC[lane*17+BR0]; q[1]=tileC[lane*17+BR1]; q[2]=tileC[lane*17+BR2]; q[3]=tileC[lane*17+BR3];
  q[4]=tileC[lane*17+BR4]; q[5]=tileC[lane*17+BR5]; q[6]=tileC[lane*17+BR6]; q[7]=tileC[lane*17+BR7];
  q[8]=tileC[lane*17+BR8]; q[9]=tileC[lane*17+BR9]; q[10]=tileC[lane*17+BR10]; q[11]=tileC[lane*17+BR11];
  q[12]=tileC[lane*17+BR12]; q[13]=tileC[lane*17+BR13]; q[14]=tileC[lane*17+BR14]; q[15]=tileC[lane*17+BR15];
  fft16r<S>(q);
#pragma unroll
  for (int i = 0; i < 16; i++) x[i] = q[i];
}

// ---------------- K0: twiddle table (k_frames only) ----------------
__global__ void k_tw() {
  int t = blockIdx.x * 256 + threadIdx.x;
  float s, c;
  sincospif((float)t * (-1.0f / 32768.0f), &s, &c);
  g_tw[t] = make_float2(c, s);
}

// ---------------- K1: routing einsum + before_upsample ----------------
__global__ void __launch_bounds__(256) k_routed(const float* __restrict__ cs,
                                                const float* __restrict__ router,
                                                float* __restrict__ out) {
  int i = blockIdx.x * 256 + threadIdx.x;
  int f = i & 127, r = (i >> 7) & 31, bc = i >> 12;
  float acc = 0.0f;
#pragma unroll
  for (int c = 0; c < 16; c++)
    acc += cs[(bc * 16 + c) * 128 + f] * router[c * 32 + r];
  g_routed[i] = acc;
  out[262144 + i] = acc;
}

// ---------------- K1b: deformation softmax ----------------
__global__ void __launch_bounds__(256) k_dw(const float* __restrict__ defs) {
  int i = blockIdx.x * 256 + threadIdx.x;
  if (i >= 1024) return;
  int f = i & 127, bc = i >> 7;
  float v[4], mx = -1e30f;
#pragma unroll
  for (int e = 0; e < 4; e++) {
    float x = defs[(bc * 4 + e) * 128 + f] + (e == 0 ? 1.0f : 0.0f);
    v[e] = x; mx = fmaxf(mx, x);
  }
  float s = 0.0f;
#pragma unroll
  for (int e = 0; e < 4; e++) { v[e] = expf(v[e] - mx); s += v[e]; }
  float inv = 1.0f / s;
#pragma unroll
  for (int e = 0; e < 4; e++) g_dw[bc * 512 + e * 128 + f] = v[e] * inv;
}

// ---------------- K2: per-frame irfft(2048) * hann (unchanged radix-2) ----------------
__global__ void __launch_bounds__(1024) k_frames(const float* __restrict__ amp,
                                                 const float* __restrict__ phase,
                                                 const float* __restrict__ decay) {
  __shared__ float2 S[2048];
  __shared__ float2 T2[1024];
  const int tid = threadIdx.x;
  const int f = blockIdx.x, re = blockIdx.y;
  const int r = re >> 2, e = re & 3;
  {
    float2 w = g_tw[tid * 32];
    T2[tid] = make_float2(w.x, -w.y);
  }
  const float fp1 = (float)(f + 1);
#pragma unroll
  for (int h = 0; h < 2; h++) {
    int n = tid + h * 1024;
    int k = (n <= 1024) ? n : (2048 - n);
    int base = (r * 1025 + k) * 4 + e;
    float av = fabsf(amp[base]);
    float dc = 0.5f + 0.45f / (1.0f + expf(-decay[base]));
    float mag = av * expf(fp1 * logf(dc + 1e-12f));
    float ph = tanhf(phase[base]) * PI_F;
    float sv, cv; sincosf(ph, &sv, &cv);
    float im = mag * sv;
    if (n > 1024) im = -im;
    S[__brev((unsigned)n) >> 21] = make_float2(mag * cv, im);
  }
  __syncthreads();
#pragma unroll
  for (int ls = 1; ls <= 11; ls++) {
    int half = 1 << (ls - 1);
    int off  = tid & (half - 1);
    int i0   = ((tid >> (ls - 1)) << ls) + off;
    int i1   = i0 + half;
    float2 w = T2[off << (11 - ls)];
    float2 a = S[i0], b = S[i1];
    float2 t = cmul(w, b);
    S[i0] = make_float2(a.x + t.x, a.y + t.y);
    S[i1] = make_float2(a.x - t.x, a.y - t.y);
    __syncthreads();
  }
  float* dst = g_frames + ((size_t)re * 32 + f) * 2048;
#pragma unroll
  for (int h = 0; h < 2; h++) {
    int t = tid + h * 1024;
    float hann = 0.5f - 0.5f * g_tw[(t * 32) & 65535].x;
    dst[t] = S[t].x * (hann * (1.0f / 2048.0f));
  }
}

// ---------------- K3: overlap-add + inv-norm ----------------
__global__ void __launch_bounds__(1024) k_oa() {
  const int re = blockIdx.x, tid = threadIdx.x;
  const float* F = g_frames + (size_t)re * 32 * 2048;
  float* R = g_res + (size_t)re * 32768;
  float ss = 0.0f;
#pragma unroll
  for (int f = 0; f < 32; f++) {
    float v = F[f * 2048 + tid];
    if (f > 0) v += F[(f - 1) * 2048 + 1024 + tid];
    R[f * 1024 + tid] = v;
    ss += v * v;
  }
#pragma unroll
  for (int o = 16; o > 0; o >>= 1) ss += __shfl_xor_sync(0xffffffffu, ss, o);
  __shared__ float red[32];
  if ((tid & 31) == 0) red[tid >> 5] = ss;
  __syncthreads();
  if (tid < 32) {
    float v = red[tid];
#pragma unroll
    for (int o = 16; o > 0; o >>= 1) v += __shfl_xor_sync(0xffffffffu, v, o);
    if (tid == 0) g_invnorm[re] = 1.0f / (sqrtf(v) + 1e-8f);
  }
}

// ---------------- K4: pass1 columns, signal (fused upsample*noise) ----------------
// mapping: lane = tid>>4 (FFT lane), c = tid&15 (column within block) -> c-fast I/O.
__global__ void __launch_bounds__(256) k_p1_sig() {
  __shared__ float2 tile[16 * 273];
  __shared__ float rrow[128];
  const int tid = threadIdx.x;
  const int lane = tid >> 4, c = tid & 15;
  const int s = blockIdx.y;
  const int b = blockIdx.x * 16 + c;
  if (tid < 128) rrow[tid] = g_routed[s * 128 + tid];
  __syncthreads();
  float2 X[16];
#pragma unroll
  for (int n2 = 0; n2 < 16; n2++) {
    float v = 0.0f;
    if (n2 < 8) {
      int j = lane + 16 * n2;       // j < 128: nonzero half
      int n = b + 256 * j;
      float pos = fminf(fmaxf((n + 0.5f) * (1.0f / 256.0f) - 0.5f, 0.0f), 127.0f);
      int lo = (int)pos;
      int hi = min(lo + 1, 127);
      float w = pos - (float)lo;
      v = (rrow[lo] * (1.0f - w) + rrow[hi] * w) * noise_pm1((unsigned)(s * 32768 + n));
    }
    X[n2] = make_float2(v, 0.0f);
  }
  fft256g<-1, true>(X, lane, tile + c * 273);
  // inter-pass twiddle e^{-2pi i * d*b/65536}, d = lane + 16*k2 (recurrence over k2)
  float sv, cv;
  __sincosf(-(TWOPI_F / 65536.0f) * (float)(lane * b), &sv, &cv);
  float2 w = make_float2(cv, sv);
  __sincosf(-(TWOPI_F / 65536.0f) * (float)(16 * b), &sv, &cv);
  float2 stp = make_float2(cv, sv);
  float2* dst = g_Fsig + (size_t)s * 65536 + b;
#pragma unroll
  for (int k2 = 0; k2 < 16; k2++) {
    dst[(lane + 16 * k2) * 256] = cmul(X[k2], w);
    w = cmul(w, stp);
  }
}

// ---------------- K5: pass1 columns, resonances ----------------
__global__ void __launch_bounds__(256) k_p1_res() {
  __shared__ float2 tile[16 * 273];
  const int tid = threadIdx.x;
  const int lane = tid >> 4, c = tid & 15;
  const int re = blockIdx.y;
  const int b = blockIdx.x * 16 + c;
  const float inv = g_invnorm[re];
  float2 X[16];
#pragma unroll
  for (int n2 = 0; n2 < 16; n2++) {
    float v = 0.0f;
    if (n2 < 8) v = g_res[(size_t)re * 32768 + b + 256 * (lane + 16 * n2)] * inv;
    X[n2] = make_float2(v, 0.0f);
  }
  fft256g<-1, true>(X, lane, tile + c * 273);
  float sv, cv;
  __sincosf(-(TWOPI_F / 65536.0f) * (float)(lane * b), &sv, &cv);
  float2 w = make_float2(cv, sv);
  __sincosf(-(TWOPI_F / 65536.0f) * (float)(16 * b), &sv, &cv);
  float2 stp = make_float2(cv, sv);
  float2* dst = g_Fres + (size_t)re * 65536 + b;
#pragma unroll
  for (int k2 = 0; k2 < 16; k2++) {
    dst[(lane + 16 * k2) * 256] = cmul(X[k2], w);
    w = cmul(w, stp);
  }
}

// ---------------- K6: pass2 rows, resonances (in-place) ----------------
// mapping: c = tid>>4 (row-of-16 within block), lane = tid&15 -> t-fast I/O, warp-local.
__global__ void __launch_bounds__(256) k_p2_res() {
  __shared__ float2 tile[16 * 273];
  const int tid = threadIdx.x;
  const int c = tid >> 4, lane = tid & 15;
  const int re = blockIdx.y;
  const int d = blockIdx.x * 16 + c;
  float2* row = g_Fres + (size_t)re * 65536 + d * 256;
  float2 X[16];
#pragma unroll
  for (int n2 = 0; n2 < 16; n2++) X[n2] = row[lane + 16 * n2];
  fft256g<-1, false>(X, lane, tile + c * 273);
#pragma unroll
  for (int k2 = 0; k2 < 16; k2++) row[lane + 16 * k2] = X[k2];
}

// ---------------- K7: fused fwd pass2(sig) + product + inverse pass1 ----------------
__global__ void __launch_bounds__(256) k_fused() {
  __shared__ float2 tile[16 * 273];
  const int tid = threadIdx.x;
  const int c = tid >> 4, lane = tid & 15;
  const int s = blockIdx.y;
  const int d = blockIdx.x * 16 + c;
  const int r = s & 31;
  const float2* srow = g_Fsig + (size_t)s * 65536 + d * 256;
  float2 X[16];
#pragma unroll
  for (int n2 = 0; n2 < 16; n2++) X[n2] = srow[lane + 16 * n2];
  fft256g<-1, false>(X, lane, tile + c * 273);
  // X[k] = Xsig[e = lane + 16k]
#pragma unroll
  for (int hb = 0; hb < 2; hb++) {
    const float2* f0 = g_Fres + (size_t)(r * 4 + 2 * hb) * 65536 + d * 256;
    const float2* f1 = f0 + 65536;
    float2 Y[16];
#pragma unroll
    for (int k = 0; k < 16; k++) {
      int e = lane + 16 * k;
      float2 a = X[k];
      float2 p0 = cmul(a, f0[e]);
      float2 p1 = cmul(a, f1[e]);
      Y[k] = make_float2(p0.x - p1.y, p0.y + p1.x);   // p0 + i*p1
    }
    __syncthreads();   // tile reuse barrier (prev dump readers / fwd fft)
    fft256g<1, false>(Y, lane, tile + c * 273);
    // Y[k2] = y[b' = lane+16k2]; twiddle e^{+2pi i b' d / 65536}, stage, dump
    float sv, cv;
    __sincosf((TWOPI_F / 65536.0f) * (float)(lane * d), &sv, &cv);
    float2 w = make_float2(cv, sv);
    __sincosf((TWOPI_F / 65536.0f) * (float)(16 * d), &sv, &cv);
    float2 stp = make_float2(cv, sv);
    float2* st = tile + c * 273;
#pragma unroll
    for (int k2 = 0; k2 < 16; k2++) {
      st[lane + 16 * k2] = cmul(Y[k2], w);
      w = cmul(w, stp);
    }
    __syncthreads();
    // coalesced dump: oc rides fast bits -> consecutive d
    const int oc = tid & 15, jb = tid >> 4;
    float2* dst = g_B + ((size_t)(s * 2 + hb)) * 65536 + blockIdx.x * 16 + oc;
    const float2* sr2 = tile + oc * 273;
#pragma unroll
    for (int m = 0; m < 16; m++) dst[(jb + 16 * m) * 256] = sr2[jb + 16 * m];
  }
}

// ---------------- K8: inverse pass2 -> packed conv ----------------
__global__ void __launch_bounds__(256) k_inv2() {
  __shared__ float2 tile[16 * 273];
  const int tid = threadIdx.x;
  const int c = tid >> 4, lane = tid & 15;
  const int pq = blockIdx.y;
  const int bp = blockIdx.x * 16 + c;   // b'
  const float2* row = g_B + (size_t)pq * 65536 + bp * 256;
  float2 X[16];
#pragma unroll
  for (int n2 = 0; n2 < 16; n2++) X[n2] = row[lane + 16 * n2];
  fft256g<1, false>(X, lane, tile + c * 273);
  // X[k2] = x[j' = lane+16k2]; keep j' < 128 (k2 < 8), scale 1/65536
  float2* st = tile + c * 273;
  const float scl = 1.0f / 65536.0f;
  __syncthreads();   // all warps done with FFT tile reads (regions per-c, safe but cheap)
#pragma unroll
  for (int k2 = 0; k2 < 8; k2++)
    st[lane + 16 * k2] = make_float2(X[k2].x * scl, X[k2].y * scl);
  __syncthreads();
  const int oc = tid & 15, jb = tid >> 4;
  float2* dst = g_conv2 + (size_t)pq * 32768 + blockIdx.x * 16 + oc;
  const float2* sr2 = tile + oc * 273;
#pragma unroll
  for (int m = 0; m < 8; m++) dst[(jb + 16 * m) * 256] = sr2[jb + 16 * m];
}

// ---------------- K9: deformation mix + tanh + sum over r ----------------
__global__ void __launch_bounds__(256) k_final2(const float* __restrict__ gains,
                                                float* __restrict__ out) {
  __shared__ float dw[512];
  __shared__ float ga[32];
  const int tid = threadIdx.x, bc = blockIdx.y;
  for (int i = tid; i < 512; i += 256) dw[i] = g_dw[bc * 512 + i];
  if (tid < 32) ga[tid] = fabsf(gains[tid]);
  __syncthreads();
  int n = blockIdx.x * 256 + tid;
  float pos = fminf(fmaxf((n + 0.5f) * (1.0f / 256.0f) - 0.5f, 0.0f), 127.0f);
  int lo = (int)pos;
  int hi = min(lo + 1, 127);
  float w = pos - (float)lo;
  float d0 = dw[lo]       * (1.0f - w) + dw[hi]       * w;
  float d1 = dw[128 + lo] * (1.0f - w) + dw[128 + hi] * w;
  float d2 = dw[256 + lo] * (1.0f - w) + dw[256 + hi] * w;
  float d3 = dw[384 + lo] * (1.0f - w) + dw[384 + hi] * w;
  float acc = 0.0f;
  const float2* cv = g_conv2 + (size_t)(bc * 32) * 2 * 32768 + n;
#pragma unroll 4
  for (int r = 0; r < 32; r++) {
    float2 v0 = cv[(size_t)(2 * r) * 32768];
    float2 v1 = cv[(size_t)(2 * r + 1) * 32768];
    float sx = d0 * v0.x + d1 * v0.y + d2 * v1.x + d3 * v1.y;
    acc += tanhf(sx * ga[r]);
  }
  out[bc * 32768 + n] = acc;
}

extern "C" void kernel_launch(void* const* d_in, const int* in_sizes, int n_in,
                              void* d_out, int out_size) {
  const float* cs     = (const float*)d_in[0];
  const float* defs   = (const float*)d_in[1];
  const float* router = (const float*)d_in[2];
  const float* amp    = (const float*)d_in[3];
  const float* phase  = (const float*)d_in[4];
  const float* decay  = (const float*)d_in[5];
  const float* gains  = (const float*)d_in[6];
  float* out = (float*)d_out;

  k_tw<<<256, 256>>>();
  k_routed<<<128, 256>>>(cs, router, out);
  k_dw<<<4, 256>>>(defs);
  k_frames<<<dim3(32, 128), 1024>>>(amp, phase, decay);
  k_oa<<<128, 1024>>>();
  k_p1_sig<<<dim3(16, 256), 256>>>();
  k_p1_res<<<dim3(16, 128), 256>>>();
  k_p2_res<<<dim3(16, 128), 256>>>();
  k_fused<<<dim3(16, 256), 256>>>();
  k_inv2<<<dim3(16, 512), 256>>>();
  k_final2<<<dim3(128, 8), 256>>>(gains, out);
}

// round 4
// speedup vs baseline: 4.7469x; 1.7116x over previous
#include <cuda_runtime.h>
#include <math.h>

#define PI_F   3.14159265358979323846f
#define TWOPI_F 6.2831853071795864769f

// ---------------- static device scratch ----------------
__device__ float  g_routed[256 * 128];
__device__ float  g_dw[8 * 4 * 128];
__device__ float  g_invnorm[128];
__device__ float2 g_spec0[128 * 1025];      // per-bin frame-0 spectrum (av*dc*e^{i ph})
__device__ float2 g_ldc2[128 * 1025];       // (log dc, dc)
__device__ float  g_frames[128 * 32 * 2048];
__device__ float  g_res[128 * 32768];
__device__ float2 g_Fsig[16777216];         // 256 x 65536  (pass1 output)
__device__ float2 g_Fres[8388608];          // 128 x 65536  (pass1 -> in-place pass2)
__device__ float2 g_B[33554432];            // 512 x 65536  (inverse pass1 output)
__device__ float  g_part[4 * 262144];       // partial r-chunk sums

__device__ __forceinline__ float2 cmul(float2 a, float2 b) {
  return make_float2(a.x * b.x - a.y * b.y, a.x * b.y + a.y * b.x);
}
__device__ __forceinline__ unsigned rotl32(unsigned x, int r) {
  return (x << r) | (x >> (32 - r));
}

// JAX threefry2x32, partitionable 32-bit path: key=(0,123), count hi=0, lo=idx,
// bits = out0 ^ out1 -> uniform [-1,1).
__device__ __forceinline__ float noise_pm1(unsigned idx) {
  const unsigned ks0 = 0u, ks1 = 123u;
  const unsigned ks2 = ks0 ^ ks1 ^ 0x1BD11BDAu;
  unsigned x0 = ks0;
  unsigned x1 = idx + ks1;
#define TFR(r) { x0 += x1; x1 = rotl32(x1, r); x1 ^= x0; }
  TFR(13) TFR(15) TFR(26) TFR(6)
  x0 += ks1; x1 += ks2 + 1u;
  TFR(17) TFR(29) TFR(16) TFR(24)
  x0 += ks2; x1 += ks0 + 2u;
  TFR(13) TFR(15) TFR(26) TFR(6)
  x0 += ks0; x1 += ks1 + 3u;
  TFR(17) TFR(29) TFR(16) TFR(24)
  x0 += ks1; x1 += ks2 + 4u;
  TFR(13) TFR(15) TFR(26) TFR(6)
  x0 += ks2; x1 += ks0 + 5u;
#undef TFR
  unsigned bits = x0 ^ x1;
  float f = __uint_as_float((bits >> 9) | 0x3f800000u) - 1.0f;
  return f * 2.0f - 1.0f;
}

// ---------------- register DFT-16 (input bit-reversed, output natural) ----------------
template <int S>
__device__ __forceinline__ void fft16r(float2* r) {
  const float C1 = 0.9238795325112867f, S1 = 0.3826834323650898f, R2 = 0.7071067811865476f;
  const float sg = (float)S;
#define BF0(i0,i1) { float ax=r[i0].x, ay=r[i0].y, bx=r[i1].x, by=r[i1].y; \
  r[i0]=make_float2(ax+bx,ay+by); r[i1]=make_float2(ax-bx,ay-by); }
#define BFI(i0,i1) { float ax=r[i0].x, ay=r[i0].y, bx=r[i1].x, by=r[i1].y; \
  float tx=-sg*by, ty=sg*bx; \
  r[i0]=make_float2(ax+tx,ay+ty); r[i1]=make_float2(ax-tx,ay-ty); }
#define BFW(i0,i1,wr,wi) { float ax=r[i0].x, ay=r[i0].y, bx=r[i1].x, by=r[i1].y; \
  float tx=(wr)*bx-(wi)*by, ty=(wr)*by+(wi)*bx; \
  r[i0]=make_float2(ax+tx,ay+ty); r[i1]=make_float2(ax-tx,ay-ty); }
  BF0(0,1) BF0(2,3) BF0(4,5) BF0(6,7) BF0(8,9) BF0(10,11) BF0(12,13) BF0(14,15)
  BF0(0,2) BFI(1,3) BF0(4,6) BFI(5,7) BF0(8,10) BFI(9,11) BF0(12,14) BFI(13,15)
  BF0(0,4) BFW(1,5, R2, sg*R2) BFI(2,6) BFW(3,7, -R2, sg*R2)
  BF0(8,12) BFW(9,13, R2, sg*R2) BFI(10,14) BFW(11,15, -R2, sg*R2)
  BF0(0,8) BFW(1,9, C1, sg*S1) BFW(2,10, R2, sg*R2) BFW(3,11, S1, sg*C1)
  BFI(4,12) BFW(5,13, -S1, sg*C1) BFW(6,14, -R2, sg*R2) BFW(7,15, -C1, sg*S1)
#undef BF0
#undef BFI
#undef BFW
}

// ---------------- register DFT-8 (input bit-reversed, output natural) ----------------
template <int S>
__device__ __forceinline__ void fft8r(float2* r) {
  const float R2 = 0.7071067811865476f;
  const float sg = (float)S;
#define BF0(i0,i1) { float ax=r[i0].x, ay=r[i0].y, bx=r[i1].x, by=r[i1].y; \
  r[i0]=make_float2(ax+bx,ay+by); r[i1]=make_float2(ax-bx,ay-by); }
#define BFI(i0,i1) { float ax=r[i0].x, ay=r[i0].y, bx=r[i1].x, by=r[i1].y; \
  float tx=-sg*by, ty=sg*bx; \
  r[i0]=make_float2(ax+tx,ay+ty); r[i1]=make_float2(ax-tx,ay-ty); }
#define BFW(i0,i1,wr,wi) { float ax=r[i0].x, ay=r[i0].y, bx=r[i1].x, by=r[i1].y; \
  float tx=(wr)*bx-(wi)*by, ty=(wr)*by+(wi)*bx; \
  r[i0]=make_float2(ax+tx,ay+ty); r[i1]=make_float2(ax-tx,ay-ty); }
  BF0(0,1) BF0(2,3) BF0(4,5) BF0(6,7)
  BF0(0,2) BFI(1,3) BF0(4,6) BFI(5,7)
  BF0(0,4) BFW(1,5, R2, sg*R2) BFI(2,6) BFW(3,7, -R2, sg*R2)
#undef BF0
#undef BFI
#undef BFW
}

// FFT-256 on 16 threads x 16 regs. Input x[n2] = v[lane + 16*n2] (natural),
// output x[k2] = V[lane + 16*k2]. tileC: per-group smem, >= 16*17 float2.
template <int S, bool BS>
__device__ __forceinline__ void fft256g(float2* x, int lane, float2* tileC) {
  const int BR0=0,BR1=8,BR2=4,BR3=12,BR4=2,BR5=10,BR6=6,BR7=14,
            BR8=1,BR9=9,BR10=5,BR11=13,BR12=3,BR13=11,BR14=7,BR15=15;
  float2 q[16];
  q[0]=x[BR0]; q[1]=x[BR1]; q[2]=x[BR2]; q[3]=x[BR3];
  q[4]=x[BR4]; q[5]=x[BR5]; q[6]=x[BR6]; q[7]=x[BR7];
  q[8]=x[BR8]; q[9]=x[BR9]; q[10]=x[BR10]; q[11]=x[BR11];
  q[12]=x[BR12]; q[13]=x[BR13]; q[14]=x[BR14]; q[15]=x[BR15];
  fft16r<S>(q);
  float sv, cv;
  __sincosf((float)S * (TWOPI_F / 256.0f) * (float)lane, &sv, &cv);
  float2 stp = make_float2(cv, sv);
  float2 w = make_float2(1.0f, 0.0f);
  if (BS) __syncthreads(); else __syncwarp();
#pragma unroll
  for (int k1 = 0; k1 < 16; k1++) {
    tileC[k1 * 17 + lane] = cmul(q[k1], w);
    w = cmul(w, stp);
  }
  if (BS) __syncthreads(); else __syncwarp();
  q[0]=tileC[lane*17+BR0]; q[1]=tileC[lane*17+BR1]; q[2]=tileC[lane*17+BR2]; q[3]=tileC[lane*17+BR3];
  q[4]=tileC[lane*17+BR4]; q[5]=tileC[lane*17+BR5]; q[6]=tileC[lane*17+BR6]; q[7]=tileC[lane*17+BR7];
  q[8]=tileC[lane*17+BR8]; q[9]=tileC[lane*17+BR9]; q[10]=tileC[lane*17+BR10]; q[11]=tileC[lane*17+BR11];
  q[12]=tileC[lane*17+BR12]; q[13]=tileC[lane*17+BR13]; q[14]=tileC[lane*17+BR14]; q[15]=tileC[lane*17+BR15];
  fft16r<S>(q);
#pragma unroll
  for (int i = 0; i < 16; i++) x[i] = q[i];
}

// ---------------- K1: routing einsum + before_upsample ----------------
__global__ void __launch_bounds__(256) k_routed(const float* __restrict__ cs,
                                                const float* __restrict__ router,
                                                float* __restrict__ out) {
  int i = blockIdx.x * 256 + threadIdx.x;
  int f = i & 127, r = (i >> 7) & 31, bc = i >> 12;
  float acc = 0.0f;
#pragma unroll
  for (int c = 0; c < 16; c++)
    acc += cs[(bc * 16 + c) * 128 + f] * router[c * 32 + r];
  g_routed[i] = acc;
  out[262144 + i] = acc;
}

// ---------------- K1b: deformation softmax ----------------
__global__ void __launch_bounds__(256) k_dw(const float* __restrict__ defs) {
  int i = blockIdx.x * 256 + threadIdx.x;
  if (i >= 1024) return;
  int f = i & 127, bc = i >> 7;
  float v[4], mx = -1e30f;
#pragma unroll
  for (int e = 0; e < 4; e++) {
    float x = defs[(bc * 4 + e) * 128 + f] + (e == 0 ? 1.0f : 0.0f);
    v[e] = x; mx = fmaxf(mx, x);
  }
  float s = 0.0f;
#pragma unroll
  for (int e = 0; e < 4; e++) { v[e] = expf(v[e] - mx); s += v[e]; }
  float inv = 1.0f / s;
#pragma unroll
  for (int e = 0; e < 4; e++) g_dw[bc * 512 + e * 128 + f] = v[e] * inv;
}

// ---------------- K2a: per-bin spectral precompute ----------------
__global__ void __launch_bounds__(256) k_spec0(const float* __restrict__ amp,
                                               const float* __restrict__ phase,
                                               const float* __restrict__ decay) {
  int k = blockIdx.x * 256 + threadIdx.x;
  if (k >= 1025) return;
  int re = blockIdx.y;
  int r = re >> 2, e = re & 3;
  int base = (r * 1025 + k) * 4 + e;
  float av = fabsf(amp[base]);
  float dc = 0.5f + 0.45f / (1.0f + expf(-decay[base]));
  float dcv = dc + 1e-12f;
  float ldc = logf(dcv);
  float ph = tanhf(phase[base]) * PI_F;
  float sv, cv; sincosf(ph, &sv, &cv);
  g_spec0[re * 1025 + k] = make_float2(av * dcv * cv, av * dcv * sv);
  g_ldc2[re * 1025 + k]  = make_float2(ldc, dcv);
}

// ---------------- K2b: paired irfft(2048)*hann via register FFT ----------------
// Block = 256 thr = 2 pair-iFFTs (frames 2p, 2p+1 packed as Re/Im).
// FFT-2048 = 8 strided FFT-256 (16-thread groups) + twiddle + DFT-8.
__global__ void __launch_bounds__(256) k_frames2() {
  __shared__ float2 SM[4640];   // [0,4368): 16 group tiles; then reused: 2x2320 transpose
  const int tid = threadIdx.x;
  const int sub = tid >> 7, lt = tid & 127;
  const int g = lt >> 4, gl = lt & 15;
  const int re = blockIdx.y;
  const int p = blockIdx.x * 2 + sub;
  const int f0 = 2 * p;
  const float2* sp0 = g_spec0 + re * 1025;
  const float2* sl  = g_ldc2  + re * 1025;
  float2 X[16];
#pragma unroll
  for (int n2 = 0; n2 < 16; n2++) {
    int n = 8 * (gl + 16 * n2) + g;
    int mir = n > 1024;
    int k = mir ? 2048 - n : n;
    float2 c0 = sp0[k];
    float2 ld = sl[k];
    float e0 = __expf((float)f0 * ld.x);
    float sx = c0.x * e0;
    float sy = (mir ? -c0.y : c0.y) * e0;
    if (n == 0 || n == 1024) sy = 0.0f;   // Hermitianize (irfft semantics)
    // z = S_f0 + i*S_f1 = S_f0*(1 + i*dc)
    X[n2] = make_float2(sx - sy * ld.y, sy + sx * ld.y);
  }
  fft256g<1, false>(X, gl, SM + (sub * 8 + g) * 273);
  __syncthreads();
  // twiddle e^{+2pi i g*k1/2048} + transpose into [k1*9+g]
  {
    float sv, cv;
    __sincosf((TWOPI_F / 2048.0f) * (float)(g * gl), &sv, &cv);
    float2 w = make_float2(cv, sv);
    __sincosf((TWOPI_F / 2048.0f) * (float)(g * 16), &sv, &cv);
    float2 stp = make_float2(cv, sv);
    float2* tp = SM + sub * 2320;
#pragma unroll
    for (int k2 = 0; k2 < 16; k2++) {
      int k1 = gl + 16 * k2;
      tp[k1 * 9 + g] = cmul(X[k2], w);
      w = cmul(w, stp);
    }
  }
  __syncthreads();
  const float2* tp = SM + sub * 2320;
  float* fa = g_frames + ((size_t)re * 32 + f0) * 2048;
  float* fb = fa + 2048;
#pragma unroll
  for (int h = 0; h < 2; h++) {
    int k1 = lt + 128 * h;
    float2 q[8];
    q[0] = tp[k1 * 9 + 0]; q[1] = tp[k1 * 9 + 4];
    q[2] = tp[k1 * 9 + 2]; q[3] = tp[k1 * 9 + 6];
    q[4] = tp[k1 * 9 + 1]; q[5] = tp[k1 * 9 + 5];
    q[6] = tp[k1 * 9 + 3]; q[7] = tp[k1 * 9 + 7];
    fft8r<1>(q);
#pragma unroll
    for (int k2 = 0; k2 < 8; k2++) {
      int t = k1 + 256 * k2;
      float sc = (0.5f - 0.5f * __cosf((TWOPI_F / 2048.0f) * (float)t)) * (1.0f / 2048.0f);
      fa[t] = q[k2].x * sc;
      fb[t] = q[k2].y * sc;
    }
  }
}

// ---------------- K3: overlap-add + inv-norm ----------------
__global__ void __launch_bounds__(1024) k_oa() {
  const int re = blockIdx.x, tid = threadIdx.x;
  const float* F = g_frames + (size_t)re * 32 * 2048;
  float* R = g_res + (size_t)re * 32768;
  float ss = 0.0f;
#pragma unroll
  for (int f = 0; f < 32; f++) {
    float v = F[f * 2048 + tid];
    if (f > 0) v += F[(f - 1) * 2048 + 1024 + tid];
    R[f * 1024 + tid] = v;
    ss += v * v;
  }
#pragma unroll
  for (int o = 16; o > 0; o >>= 1) ss += __shfl_xor_sync(0xffffffffu, ss, o);
  __shared__ float red[32];
  if ((tid & 31) == 0) red[tid >> 5] = ss;
  __syncthreads();
  if (tid < 32) {
    float v = red[tid];
#pragma unroll
    for (int o = 16; o > 0; o >>= 1) v += __shfl_xor_sync(0xffffffffu, v, o);
    if (tid == 0) g_invnorm[re] = 1.0f / (sqrtf(v) + 1e-8f);
  }
}

// ---------------- K4: pass1 columns, signal (fused upsample*noise) ----------------
__global__ void __launch_bounds__(256) k_p1_sig() {
  __shared__ float2 tile[16 * 273];
  __shared__ float rrow[128];
  const int tid = threadIdx.x;
  const int lane = tid >> 4, c = tid & 15;
  const int s = blockIdx.y;
  const int b = blockIdx.x * 16 + c;
  if (tid < 128) rrow[tid] = g_routed[s * 128 + tid];
  __syncthreads();
  float2 X[16];
#pragma unroll
  for (int n2 = 0; n2 < 16; n2++) {
    float v = 0.0f;
    if (n2 < 8) {
      int j = lane + 16 * n2;
      int n = b + 256 * j;
      float pos = fminf(fmaxf((n + 0.5f) * (1.0f / 256.0f) - 0.5f, 0.0f), 127.0f);
      int lo = (int)pos;
      int hi = min(lo + 1, 127);
      float w = pos - (float)lo;
      v = (rrow[lo] * (1.0f - w) + rrow[hi] * w) * noise_pm1((unsigned)(s * 32768 + n));
    }
    X[n2] = make_float2(v, 0.0f);
  }
  fft256g<-1, true>(X, lane, tile + c * 273);
  float sv, cv;
  __sincosf(-(TWOPI_F / 65536.0f) * (float)(lane * b), &sv, &cv);
  float2 w = make_float2(cv, sv);
  __sincosf(-(TWOPI_F / 65536.0f) * (float)(16 * b), &sv, &cv);
  float2 stp = make_float2(cv, sv);
  float2* dst = g_Fsig + (size_t)s * 65536 + b;
#pragma unroll
  for (int k2 = 0; k2 < 16; k2++) {
    dst[(lane + 16 * k2) * 256] = cmul(X[k2], w);
    w = cmul(w, stp);
  }
}

// ---------------- K5: pass1 columns, resonances ----------------
__global__ void __launch_bounds__(256) k_p1_res() {
  __shared__ float2 tile[16 * 273];
  const int tid = threadIdx.x;
  const int lane = tid >> 4, c = tid & 15;
  const int re = blockIdx.y;
  const int b = blockIdx.x * 16 + c;
  const float inv = g_invnorm[re];
  float2 X[16];
#pragma unroll
  for (int n2 = 0; n2 < 16; n2++) {
    float v = 0.0f;
    if (n2 < 8) v = g_res[(size_t)re * 32768 + b + 256 * (lane + 16 * n2)] * inv;
    X[n2] = make_float2(v, 0.0f);
  }
  fft256g<-1, true>(X, lane, tile + c * 273);
  float sv, cv;
  __sincosf(-(TWOPI_F / 65536.0f) * (float)(lane * b), &sv, &cv);
  float2 w = make_float2(cv, sv);
  __sincosf(-(TWOPI_F / 65536.0f) * (float)(16 * b), &sv, &cv);
  float2 stp = make_float2(cv, sv);
  float2* dst = g_Fres + (size_t)re * 65536 + b;
#pragma unroll
  for (int k2 = 0; k2 < 16; k2++) {
    dst[(lane + 16 * k2) * 256] = cmul(X[k2], w);
    w = cmul(w, stp);
  }
}

// ---------------- K6: pass2 rows, resonances (in-place) ----------------
__global__ void __launch_bounds__(256) k_p2_res() {
  __shared__ float2 tile[16 * 273];
  const int tid = threadIdx.x;
  const int c = tid >> 4, lane = tid & 15;
  const int re = blockIdx.y;
  const int d = blockIdx.x * 16 + c;
  float2* row = g_Fres + (size_t)re * 65536 + d * 256;
  float2 X[16];
#pragma unroll
  for (int n2 = 0; n2 < 16; n2++) X[n2] = row[lane + 16 * n2];
  fft256g<-1, false>(X, lane, tile + c * 273);
#pragma unroll
  for (int k2 = 0; k2 < 16; k2++) row[lane + 16 * k2] = X[k2];
}

// ---------------- K7: fused fwd pass2(sig) + product + inverse pass1 ----------------
// grid (16 dblocks, 32 r); loops the 8 bc values so Fres segments stay L2-hot.
__global__ void __launch_bounds__(256) k_fused2() {
  __shared__ float2 tile[16 * 273];
  const int tid = threadIdx.x;
  const int c = tid >> 4, lane = tid & 15;
  const int r = blockIdx.y;
  const int d = blockIdx.x * 16 + c;
  for (int bc = 0; bc < 8; bc++) {
    const int s = bc * 32 + r;
    const float2* srow = g_Fsig + (size_t)s * 65536 + d * 256;
    float2 X[16];
#pragma unroll
    for (int n2 = 0; n2 < 16; n2++) X[n2] = srow[lane + 16 * n2];
    fft256g<-1, false>(X, lane, tile + c * 273);
#pragma unroll
    for (int hb = 0; hb < 2; hb++) {
      const float2* f0 = g_Fres + (size_t)(r * 4 + 2 * hb) * 65536 + d * 256;
      const float2* f1 = f0 + 65536;
      float2 Y[16];
#pragma unroll
      for (int k = 0; k < 16; k++) {
        int e = lane + 16 * k;
        float2 a = X[k];
        float2 p0 = cmul(a, f0[e]);
        float2 p1 = cmul(a, f1[e]);
        Y[k] = make_float2(p0.x - p1.y, p0.y + p1.x);   // p0 + i*p1
      }
      fft256g<1, false>(Y, lane, tile + c * 273);
      float sv, cv;
      __sincosf((TWOPI_F / 65536.0f) * (float)(lane * d), &sv, &cv);
      float2 w = make_float2(cv, sv);
      __sincosf((TWOPI_F / 65536.0f) * (float)(16 * d), &sv, &cv);
      float2 stp = make_float2(cv, sv);
      float2* st = tile + c * 273;
      __syncwarp();
#pragma unroll
      for (int k2 = 0; k2 < 16; k2++) {
        st[lane + 16 * k2] = cmul(Y[k2], w);
        w = cmul(w, stp);
      }
      __syncthreads();
      const int oc = tid & 15, jb = tid >> 4;
      float2* dst = g_B + ((size_t)(s * 2 + hb)) * 65536 + blockIdx.x * 16 + oc;
      const float2* sr2 = tile + oc * 273;
#pragma unroll
      for (int m = 0; m < 16; m++) dst[(jb + 16 * m) * 256] = sr2[jb + 16 * m];
      __syncthreads();
    }
  }
}

// ---------------- K8: fused inverse pass2 + deformation mix + tanh (partial r-sum) ----------------
__global__ void __launch_bounds__(256) k_invfinal(const float* __restrict__ gains) {
  __shared__ float2 tile[16 * 273];
  __shared__ float dw[512];
  __shared__ float ga[32];
  const int tid = threadIdx.x;
  const int c = tid >> 4, lane = tid & 15;
  const int bc = blockIdx.y, rz = blockIdx.z;
  const int bp = blockIdx.x * 16 + c;
  for (int i = tid; i < 512; i += 256) dw[i] = g_dw[bc * 512 + i];
  if (tid < 32) ga[tid] = fabsf(gains[tid]);
  __syncthreads();
  float d0[8], d1[8], d2[8], d3[8], accv[8];
  const float scl = 1.0f / 65536.0f;
#pragma unroll
  for (int k2 = 0; k2 < 8; k2++) {
    int n = bp + 256 * (lane + 16 * k2);
    float pos = fminf(fmaxf((n + 0.5f) * (1.0f / 256.0f) - 0.5f, 0.0f), 127.0f);
    int lo = (int)pos;
    int hi = min(lo + 1, 127);
    float w = pos - (float)lo;
    d0[k2] = (dw[lo]       * (1.0f - w) + dw[hi]       * w) * scl;
    d1[k2] = (dw[128 + lo] * (1.0f - w) + dw[128 + hi] * w) * scl;
    d2[k2] = (dw[256 + lo] * (1.0f - w) + dw[256 + hi] * w) * scl;
    d3[k2] = (dw[384 + lo] * (1.0f - w) + dw[384 + hi] * w) * scl;
    accv[k2] = 0.0f;
  }
  for (int rr = 0; rr < 8; rr++) {
    const int r = rz * 8 + rr;
    const size_t base = ((size_t)((bc * 32 + r) * 2)) * 65536 + (size_t)bp * 256;
    float2 Y0[8];
    {
      const float2* row = g_B + base;
      float2 X[16];
#pragma unroll
      for (int n2 = 0; n2 < 16; n2++) X[n2] = row[lane + 16 * n2];
      fft256g<1, false>(X, lane, tile + c * 273);
#pragma unroll
      for (int k2 = 0; k2 < 8; k2++) Y0[k2] = X[k2];
    }
    float2 X[16];
    {
      const float2* row = g_B + base + 65536;
#pragma unroll
      for (int n2 = 0; n2 < 16; n2++) X[n2] = row[lane + 16 * n2];
      fft256g<1, false>(X, lane, tile + c * 273);
    }
    const float gn = ga[r];
#pragma unroll
    for (int k2 = 0; k2 < 8; k2++) {
      float sx = d0[k2] * Y0[k2].x + d1[k2] * Y0[k2].y + d2[k2] * X[k2].x + d3[k2] * X[k2].y;
      sx = fminf(fmaxf(sx * gn, -15.0f), 15.0f);
      float z = __expf(2.0f * sx);
      accv[k2] += __fdividef(z - 1.0f, z + 1.0f);
    }
  }
  float* dst = g_part + (size_t)rz * 262144 + bc * 32768;
#pragma unroll
  for (int k2 = 0; k2 < 8; k2++) {
    int n = bp + 256 * (lane + 16 * k2);
    dst[n] = accv[k2];
  }
}

// ---------------- K9: reduce 4 partials into output ----------------
__global__ void __launch_bounds__(256) k_reduce(float* __restrict__ out) {
  int i = blockIdx.x * 256 + threadIdx.x;  // 262144
  out[i] = g_part[i] + g_part[262144 + i] + g_part[524288 + i] + g_part[786432 + i];
}

extern "C" void kernel_launch(void* const* d_in, const int* in_sizes, int n_in,
                              void* d_out, int out_size) {
  const float* cs     = (const float*)d_in[0];
  const float* defs   = (const float*)d_in[1];
  const float* router = (const float*)d_in[2];
  const float* amp    = (const float*)d_in[3];
  const float* phase  = (const float*)d_in[4];
  const float* decay  = (const float*)d_in[5];
  const float* gains  = (const float*)d_in[6];
  float* out = (float*)d_out;

  k_routed<<<128, 256>>>(cs, router, out);
  k_dw<<<4, 256>>>(defs);
  k_spec0<<<dim3(5, 128), 256>>>(amp, phase, decay);
  k_frames2<<<dim3(8, 128), 256>>>();
  k_oa<<<128, 1024>>>();
  k_p1_sig<<<dim3(16, 256), 256>>>();
  k_p1_res<<<dim3(16, 128), 256>>>();
  k_p2_res<<<dim3(16, 128), 256>>>();
  k_fused2<<<dim3(16, 32), 256>>>();
  k_invfinal<<<dim3(16, 8, 4), 256>>>(gains);
  k_reduce<<<1024, 256>>>(out);
}

// round 5
// speedup vs baseline: 4.8485x; 1.0214x over previous
#include <cuda_runtime.h>
#include <cuda_fp16.h>
#include <math.h>

#define PI_F   3.14159265358979323846f
#define TWOPI_F 6.2831853071795864769f

// ---------------- static device scratch ----------------
__device__ float   g_routed[256 * 128];
__device__ float   g_dw[8 * 4 * 128];
__device__ float   g_invnorm[128];
__device__ float2  g_spec0[128 * 1025];      // per-bin frame-0 spectrum (av*dc*e^{i ph})
__device__ float2  g_ldc2[128 * 1025];       // (log dc, dc)
__device__ float   g_frames[128 * 32 * 2048];
__device__ float   g_res[128 * 32768];
__device__ float2  g_Fsig[16777216];         // 256 x 65536  (pass1 output)
__device__ float2  g_Fres[8388608];          // 128 x 65536  (pass1 -> in-place pass2 in k_fused3)
__device__ __half2 g_B[33554432];            // 512 x 65536  (inverse pass1, pre-scaled, fp16)
__device__ float   g_part[4 * 262144];       // partial r-chunk sums

__device__ __forceinline__ float2 cmul(float2 a, float2 b) {
  return make_float2(a.x * b.x - a.y * b.y, a.x * b.y + a.y * b.x);
}
__device__ __forceinline__ unsigned rotl32(unsigned x, int r) {
  return (x << r) | (x >> (32 - r));
}

// JAX threefry2x32, partitionable 32-bit path: key=(0,123), count hi=0, lo=idx,
// bits = out0 ^ out1 -> uniform [-1,1).
__device__ __forceinline__ float noise_pm1(unsigned idx) {
  const unsigned ks0 = 0u, ks1 = 123u;
  const unsigned ks2 = ks0 ^ ks1 ^ 0x1BD11BDAu;
  unsigned x0 = ks0;
  unsigned x1 = idx + ks1;
#define TFR(r) { x0 += x1; x1 = rotl32(x1, r); x1 ^= x0; }
  TFR(13) TFR(15) TFR(26) TFR(6)
  x0 += ks1; x1 += ks2 + 1u;
  TFR(17) TFR(29) TFR(16) TFR(24)
  x0 += ks2; x1 += ks0 + 2u;
  TFR(13) TFR(15) TFR(26) TFR(6)
  x0 += ks0; x1 += ks1 + 3u;
  TFR(17) TFR(29) TFR(16) TFR(24)
  x0 += ks1; x1 += ks2 + 4u;
  TFR(13) TFR(15) TFR(26) TFR(6)
  x0 += ks2; x1 += ks0 + 5u;
#undef TFR
  unsigned bits = x0 ^ x1;
  float f = __uint_as_float((bits >> 9) | 0x3f800000u) - 1.0f;
  return f * 2.0f - 1.0f;
}

// ---------------- register DFT-16 (input bit-reversed, output natural) ----------------
template <int S>
__device__ __forceinline__ void fft16r(float2* r) {
  const float C1 = 0.9238795325112867f, S1 = 0.3826834323650898f, R2 = 0.7071067811865476f;
  const float sg = (float)S;
#define BF0(i0,i1) { float ax=r[i0].x, ay=r[i0].y, bx=r[i1].x, by=r[i1].y; \
  r[i0]=make_float2(ax+bx,ay+by); r[i1]=make_float2(ax-bx,ay-by); }
#define BFI(i0,i1) { float ax=r[i0].x, ay=r[i0].y, bx=r[i1].x, by=r[i1].y; \
  float tx=-sg*by, ty=sg*bx; \
  r[i0]=make_float2(ax+tx,ay+ty); r[i1]=make_float2(ax-tx,ay-ty); }
#define BFW(i0,i1,wr,wi) { float ax=r[i0].x, ay=r[i0].y, bx=r[i1].x, by=r[i1].y; \
  float tx=(wr)*bx-(wi)*by, ty=(wr)*by+(wi)*bx; \
  r[i0]=make_float2(ax+tx,ay+ty); r[i1]=make_float2(ax-tx,ay-ty); }
  BF0(0,1) BF0(2,3) BF0(4,5) BF0(6,7) BF0(8,9) BF0(10,11) BF0(12,13) BF0(14,15)
  BF0(0,2) BFI(1,3) BF0(4,6) BFI(5,7) BF0(8,10) BFI(9,11) BF0(12,14) BFI(13,15)
  BF0(0,4) BFW(1,5, R2, sg*R2) BFI(2,6) BFW(3,7, -R2, sg*R2)
  BF0(8,12) BFW(9,13, R2, sg*R2) BFI(10,14) BFW(11,15, -R2, sg*R2)
  BF0(0,8) BFW(1,9, C1, sg*S1) BFW(2,10, R2, sg*R2) BFW(3,11, S1, sg*C1)
  BFI(4,12) BFW(5,13, -S1, sg*C1) BFW(6,14, -R2, sg*R2) BFW(7,15, -C1, sg*S1)
#undef BF0
#undef BFI
#undef BFW
}

// ---------------- register DFT-8 (input bit-reversed, output natural) ----------------
template <int S>
__device__ __forceinline__ void fft8r(float2* r) {
  const float R2 = 0.7071067811865476f;
  const float sg = (float)S;
#define BF0(i0,i1) { float ax=r[i0].x, ay=r[i0].y, bx=r[i1].x, by=r[i1].y; \
  r[i0]=make_float2(ax+bx,ay+by); r[i1]=make_float2(ax-bx,ay-by); }
#define BFI(i0,i1) { float ax=r[i0].x, ay=r[i0].y, bx=r[i1].x, by=r[i1].y; \
  float tx=-sg*by, ty=sg*bx; \
  r[i0]=make_float2(ax+tx,ay+ty); r[i1]=make_float2(ax-tx,ay-ty); }
#define BFW(i0,i1,wr,wi) { float ax=r[i0].x, ay=r[i0].y, bx=r[i1].x, by=r[i1].y; \
  float tx=(wr)*bx-(wi)*by, ty=(wr)*by+(wi)*bx; \
  r[i0]=make_float2(ax+tx,ay+ty); r[i1]=make_float2(ax-tx,ay-ty); }
  BF0(0,1) BF0(2,3) BF0(4,5) BF0(6,7)
  BF0(0,2) BFI(1,3) BF0(4,6) BFI(5,7)
  BF0(0,4) BFW(1,5, R2, sg*R2) BFI(2,6) BFW(3,7, -R2, sg*R2)
#undef BF0
#undef BFI
#undef BFW
}

// FFT-256 on 16 threads x 16 regs. Input x[n2] = v[lane + 16*n2] (natural),
// output x[k2] = V[lane + 16*k2]. tileC: per-group smem, >= 16*17 float2.
template <int S, bool BS>
__device__ __forceinline__ void fft256g(float2* x, int lane, float2* tileC) {
  const int BR0=0,BR1=8,BR2=4,BR3=12,BR4=2,BR5=10,BR6=6,BR7=14,
            BR8=1,BR9=9,BR10=5,BR11=13,BR12=3,BR13=11,BR14=7,BR15=15;
  float2 q[16];
  q[0]=x[BR0]; q[1]=x[BR1]; q[2]=x[BR2]; q[3]=x[BR3];
  q[4]=x[BR4]; q[5]=x[BR5]; q[6]=x[BR6]; q[7]=x[BR7];
  q[8]=x[BR8]; q[9]=x[BR9]; q[10]=x[BR10]; q[11]=x[BR11];
  q[12]=x[BR12]; q[13]=x[BR13]; q[14]=x[BR14]; q[15]=x[BR15];
  fft16r<S>(q);
  float sv, cv;
  __sincosf((float)S * (TWOPI_F / 256.0f) * (float)lane, &sv, &cv);
  float2 stp = make_float2(cv, sv);
  float2 w = make_float2(1.0f, 0.0f);
  if (BS) __syncthreads(); else __syncwarp();
#pragma unroll
  for (int k1 = 0; k1 < 16; k1++) {
    tileC[k1 * 17 + lane] = cmul(q[k1], w);
    w = cmul(w, stp);
  }
  if (BS) __syncthreads(); else __syncwarp();
  q[0]=tileC[lane*17+BR0]; q[1]=tileC[lane*17+BR1]; q[2]=tileC[lane*17+BR2]; q[3]=tileC[lane*17+BR3];
  q[4]=tileC[lane*17+BR4]; q[5]=tileC[lane*17+BR5]; q[6]=tileC[lane*17+BR6]; q[7]=tileC[lane*17+BR7];
  q[8]=tileC[lane*17+BR8]; q[9]=tileC[lane*17+BR9]; q[10]=tileC[lane*17+BR10]; q[11]=tileC[lane*17+BR11];
  q[12]=tileC[lane*17+BR12]; q[13]=tileC[lane*17+BR13]; q[14]=tileC[lane*17+BR14]; q[15]=tileC[lane*17+BR15];
  fft16r<S>(q);
#pragma unroll
  for (int i = 0; i < 16; i++) x[i] = q[i];
}

// ---------------- K1: routing einsum + before_upsample ----------------
__global__ void __launch_bounds__(256) k_routed(const float* __restrict__ cs,
                                                const float* __restrict__ router,
                                                float* __restrict__ out) {
  int i = blockIdx.x * 256 + threadIdx.x;
  int f = i & 127, r = (i >> 7) & 31, bc = i >> 12;
  float acc = 0.0f;
#pragma unroll
  for (int c = 0; c < 16; c++)
    acc += cs[(bc * 16 + c) * 128 + f] * router[c * 32 + r];
  g_routed[i] = acc;
  out[262144 + i] = acc;
}

// ---------------- K1b: deformation softmax ----------------
__global__ void __launch_bounds__(256) k_dw(const float* __restrict__ defs) {
  int i = blockIdx.x * 256 + threadIdx.x;
  if (i >= 1024) return;
  int f = i & 127, bc = i >> 7;
  float v[4], mx = -1e30f;
#pragma unroll
  for (int e = 0; e < 4; e++) {
    float x = defs[(bc * 4 + e) * 128 + f] + (e == 0 ? 1.0f : 0.0f);
    v[e] = x; mx = fmaxf(mx, x);
  }
  float s = 0.0f;
#pragma unroll
  for (int e = 0; e < 4; e++) { v[e] = expf(v[e] - mx); s += v[e]; }
  float inv = 1.0f / s;
#pragma unroll
  for (int e = 0; e < 4; e++) g_dw[bc * 512 + e * 128 + f] = v[e] * inv;
}

// ---------------- K2a: per-bin spectral precompute ----------------
__global__ void __launch_bounds__(256) k_spec0(const float* __restrict__ amp,
                                               const float* __restrict__ phase,
                                               const float* __restrict__ decay) {
  int k = blockIdx.x * 256 + threadIdx.x;
  if (k >= 1025) return;
  int re = blockIdx.y;
  int r = re >> 2, e = re & 3;
  int base = (r * 1025 + k) * 4 + e;
  float av = fabsf(amp[base]);
  float dc = 0.5f + 0.45f / (1.0f + expf(-decay[base]));
  float dcv = dc + 1e-12f;
  float ldc = logf(dcv);
  float ph = tanhf(phase[base]) * PI_F;
  float sv, cv; sincosf(ph, &sv, &cv);
  g_spec0[re * 1025 + k] = make_float2(av * dcv * cv, av * dcv * sv);
  g_ldc2[re * 1025 + k]  = make_float2(ldc, dcv);
}

// ---------------- K2b: paired irfft(2048)*hann via register FFT ----------------
__global__ void __launch_bounds__(256) k_frames2() {
  __shared__ float2 SM[4640];
  const int tid = threadIdx.x;
  const int sub = tid >> 7, lt = tid & 127;
  const int g = lt >> 4, gl = lt & 15;
  const int re = blockIdx.y;
  const int p = blockIdx.x * 2 + sub;
  const int f0 = 2 * p;
  const float2* sp0 = g_spec0 + re * 1025;
  const float2* sl  = g_ldc2  + re * 1025;
  float2 X[16];
#pragma unroll
  for (int n2 = 0; n2 < 16; n2++) {
    int n = 8 * (gl + 16 * n2) + g;
    int mir = n > 1024;
    int k = mir ? 2048 - n : n;
    float2 c0 = sp0[k];
    float2 ld = sl[k];
    float e0 = __expf((float)f0 * ld.x);
    float sx = c0.x * e0;
    float sy = (mir ? -c0.y : c0.y) * e0;
    if (n == 0 || n == 1024) sy = 0.0f;
    X[n2] = make_float2(sx - sy * ld.y, sy + sx * ld.y);
  }
  fft256g<1, false>(X, gl, SM + (sub * 8 + g) * 273);
  __syncthreads();
  {
    float sv, cv;
    __sincosf((TWOPI_F / 2048.0f) * (float)(g * gl), &sv, &cv);
    float2 w = make_float2(cv, sv);
    __sincosf((TWOPI_F / 2048.0f) * (float)(g * 16), &sv, &cv);
    float2 stp = make_float2(cv, sv);
    float2* tp = SM + sub * 2320;
#pragma unroll
    for (int k2 = 0; k2 < 16; k2++) {
      int k1 = gl + 16 * k2;
      tp[k1 * 9 + g] = cmul(X[k2], w);
      w = cmul(w, stp);
    }
  }
  __syncthreads();
  const float2* tp = SM + sub * 2320;
  float* fa = g_frames + ((size_t)re * 32 + f0) * 2048;
  float* fb = fa + 2048;
#pragma unroll
  for (int h = 0; h < 2; h++) {
    int k1 = lt + 128 * h;
    float2 q[8];
    q[0] = tp[k1 * 9 + 0]; q[1] = tp[k1 * 9 + 4];
    q[2] = tp[k1 * 9 + 2]; q[3] = tp[k1 * 9 + 6];
    q[4] = tp[k1 * 9 + 1]; q[5] = tp[k1 * 9 + 5];
    q[6] = tp[k1 * 9 + 3]; q[7] = tp[k1 * 9 + 7];
    fft8r<1>(q);
#pragma unroll
    for (int k2 = 0; k2 < 8; k2++) {
      int t = k1 + 256 * k2;
      float sc = (0.5f - 0.5f * __cosf((TWOPI_F / 2048.0f) * (float)t)) * (1.0f / 2048.0f);
      fa[t] = q[k2].x * sc;
      fb[t] = q[k2].y * sc;
    }
  }
}

// ---------------- K3: overlap-add + inv-norm ----------------
__global__ void __launch_bounds__(1024) k_oa() {
  const int re = blockIdx.x, tid = threadIdx.x;
  const float* F = g_frames + (size_t)re * 32 * 2048;
  float* R = g_res + (size_t)re * 32768;
  float ss = 0.0f;
#pragma unroll
  for (int f = 0; f < 32; f++) {
    float v = F[f * 2048 + tid];
    if (f > 0) v += F[(f - 1) * 2048 + 1024 + tid];
    R[f * 1024 + tid] = v;
    ss += v * v;
  }
#pragma unroll
  for (int o = 16; o > 0; o >>= 1) ss += __shfl_xor_sync(0xffffffffu, ss, o);
  __shared__ float red[32];
  if ((tid & 31) == 0) red[tid >> 5] = ss;
  __syncthreads();
  if (tid < 32) {
    float v = red[tid];
#pragma unroll
    for (int o = 16; o > 0; o >>= 1) v += __shfl_xor_sync(0xffffffffu, v, o);
    if (tid == 0) g_invnorm[re] = 1.0f / (sqrtf(v) + 1e-8f);
  }
}

// ---------------- K4: pass1 columns, signal (fused upsample*noise) ----------------
__global__ void __launch_bounds__(256) k_p1_sig() {
  __shared__ float2 tile[16 * 273];
  __shared__ float rrow[128];
  const int tid = threadIdx.x;
  const int lane = tid >> 4, c = tid & 15;
  const int s = blockIdx.y;
  const int b = blockIdx.x * 16 + c;
  if (tid < 128) rrow[tid] = g_routed[s * 128 + tid];
  __syncthreads();
  float2 X[16];
#pragma unroll
  for (int n2 = 0; n2 < 16; n2++) {
    float v = 0.0f;
    if (n2 < 8) {
      int j = lane + 16 * n2;
      int n = b + 256 * j;
      float pos = fminf(fmaxf((n + 0.5f) * (1.0f / 256.0f) - 0.5f, 0.0f), 127.0f);
      int lo = (int)pos;
      int hi = min(lo + 1, 127);
      float w = pos - (float)lo;
      v = (rrow[lo] * (1.0f - w) + rrow[hi] * w) * noise_pm1((unsigned)(s * 32768 + n));
    }
    X[n2] = make_float2(v, 0.0f);
  }
  fft256g<-1, true>(X, lane, tile + c * 273);
  float sv, cv;
  __sincosf(-(TWOPI_F / 65536.0f) * (float)(lane * b), &sv, &cv);
  float2 w = make_float2(cv, sv);
  __sincosf(-(TWOPI_F / 65536.0f) * (float)(16 * b), &sv, &cv);
  float2 stp = make_float2(cv, sv);
  float2* dst = g_Fsig + (size_t)s * 65536 + b;
#pragma unroll
  for (int k2 = 0; k2 < 16; k2++) {
    dst[(lane + 16 * k2) * 256] = cmul(X[k2], w);
    w = cmul(w, stp);
  }
}

// ---------------- K5: pass1 columns, resonances ----------------
__global__ void __launch_bounds__(256) k_p1_res() {
  __shared__ float2 tile[16 * 273];
  const int tid = threadIdx.x;
  const int lane = tid >> 4, c = tid & 15;
  const int re = blockIdx.y;
  const int b = blockIdx.x * 16 + c;
  const float inv = g_invnorm[re];
  float2 X[16];
#pragma unroll
  for (int n2 = 0; n2 < 16; n2++) {
    float v = 0.0f;
    if (n2 < 8) v = g_res[(size_t)re * 32768 + b + 256 * (lane + 16 * n2)] * inv;
    X[n2] = make_float2(v, 0.0f);
  }
  fft256g<-1, true>(X, lane, tile + c * 273);
  float sv, cv;
  __sincosf(-(TWOPI_F / 65536.0f) * (float)(lane * b), &sv, &cv);
  float2 w = make_float2(cv, sv);
  __sincosf(-(TWOPI_F / 65536.0f) * (float)(16 * b), &sv, &cv);
  float2 stp = make_float2(cv, sv);
  float2* dst = g_Fres + (size_t)re * 65536 + b;
#pragma unroll
  for (int k2 = 0; k2 < 16; k2++) {
    dst[(lane + 16 * k2) * 256] = cmul(X[k2], w);
    w = cmul(w, stp);
  }
}

// ---------------- K7: fused res-pass2 + fwd pass2(sig) + product + inverse pass1 ----------------
// grid (16 dblocks, 32 r). Block (dblk, r) owns Fres rows re in [4r,4r+4) x its
// 16 d-rows: exact partition, so res-pass2 runs in-place here with no cross-block deps.
__global__ void __launch_bounds__(256) k_fused3() {
  __shared__ float2 tile[16 * 273];
  const int tid = threadIdx.x;
  const int c = tid >> 4, lane = tid & 15;
  const int r = blockIdx.y;
  const int d = blockIdx.x * 16 + c;
  // --- inline res pass2 for this block's rows ---
#pragma unroll
  for (int re4 = 0; re4 < 4; re4++) {
    float2* row = g_Fres + (size_t)(r * 4 + re4) * 65536 + d * 256;
    float2 X[16];
#pragma unroll
    for (int n2 = 0; n2 < 16; n2++) X[n2] = row[lane + 16 * n2];
    fft256g<-1, false>(X, lane, tile + c * 273);
#pragma unroll
    for (int k2 = 0; k2 < 16; k2++) row[lane + 16 * k2] = X[k2];
  }
  __syncwarp();   // group-private write->read ordering
  for (int bc = 0; bc < 8; bc++) {
    const int s = bc * 32 + r;
    const float2* srow = g_Fsig + (size_t)s * 65536 + d * 256;
    float2 X[16];
#pragma unroll
    for (int n2 = 0; n2 < 16; n2++) X[n2] = srow[lane + 16 * n2];
    fft256g<-1, false>(X, lane, tile + c * 273);
#pragma unroll
    for (int hb = 0; hb < 2; hb++) {
      const float2* f0 = g_Fres + (size_t)(r * 4 + 2 * hb) * 65536 + d * 256;
      const float2* f1 = f0 + 65536;
      float2 Y[16];
#pragma unroll
      for (int k = 0; k < 16; k++) {
        int e = lane + 16 * k;
        float2 a = X[k];
        float2 p0 = cmul(a, f0[e]);
        float2 p1 = cmul(a, f1[e]);
        Y[k] = make_float2(p0.x - p1.y, p0.y + p1.x);   // p0 + i*p1
      }
      fft256g<1, false>(Y, lane, tile + c * 273);
      // twiddle (scaled by 1/65536 for fp16 range) + stage + dump
      float sv, cv;
      __sincosf((TWOPI_F / 65536.0f) * (float)(lane * d), &sv, &cv);
      const float scl = 1.0f / 65536.0f;
      float2 w = make_float2(cv * scl, sv * scl);
      __sincosf((TWOPI_F / 65536.0f) * (float)(16 * d), &sv, &cv);
      float2 stp = make_float2(cv, sv);
      float2* st = tile + c * 273;
      __syncwarp();
#pragma unroll
      for (int k2 = 0; k2 < 16; k2++) {
        st[lane + 16 * k2] = cmul(Y[k2], w);
        w = cmul(w, stp);
      }
      __syncthreads();
      const int oc = tid & 15, jb = tid >> 4;
      __half2* dst = g_B + ((size_t)(s * 2 + hb)) * 65536 + blockIdx.x * 16 + oc;
      const float2* sr2 = tile + oc * 273;
#pragma unroll
      for (int m = 0; m < 16; m++) {
        float2 z = sr2[jb + 16 * m];
        dst[(jb + 16 * m) * 256] = __floats2half2_rn(z.x, z.y);
      }
      __syncthreads();
    }
  }
}

// ---------------- K8: fused inverse pass2 + deformation mix + tanh (partial r-sum) ----------------
__global__ void __launch_bounds__(256) k_invfinal(const float* __restrict__ gains) {
  __shared__ float2 tile[16 * 273];
  __shared__ float dw[512];
  __shared__ float ga[32];
  const int tid = threadIdx.x;
  const int c = tid >> 4, lane = tid & 15;
  const int bc = blockIdx.y, rz = blockIdx.z;
  const int bp = blockIdx.x * 16 + c;
  for (int i = tid; i < 512; i += 256) dw[i] = g_dw[bc * 512 + i];
  if (tid < 32) ga[tid] = fabsf(gains[tid]);
  __syncthreads();
  float d0[8], d1[8], d2[8], d3[8], accv[8];
#pragma unroll
  for (int k2 = 0; k2 < 8; k2++) {
    int n = bp + 256 * (lane + 16 * k2);
    float pos = fminf(fmaxf((n + 0.5f) * (1.0f / 256.0f) - 0.5f, 0.0f), 127.0f);
    int lo = (int)pos;
    int hi = min(lo + 1, 127);
    float w = pos - (float)lo;
    d0[k2] = dw[lo]       * (1.0f - w) + dw[hi]       * w;
    d1[k2] = dw[128 + lo] * (1.0f - w) + dw[128 + hi] * w;
    d2[k2] = dw[256 + lo] * (1.0f - w) + dw[256 + hi] * w;
    d3[k2] = dw[384 + lo] * (1.0f - w) + dw[384 + hi] * w;
    accv[k2] = 0.0f;
  }
  for (int rr = 0; rr < 8; rr++) {
    const int r = rz * 8 + rr;
    const size_t base = ((size_t)((bc * 32 + r) * 2)) * 65536 + (size_t)bp * 256;
    float2 Y0[8];
    {
      const __half2* row = g_B + base;
      float2 X[16];
#pragma unroll
      for (int n2 = 0; n2 < 16; n2++) X[n2] = __half22float2(row[lane + 16 * n2]);
      fft256g<1, false>(X, lane, tile + c * 273);
#pragma unroll
      for (int k2 = 0; k2 < 8; k2++) Y0[k2] = X[k2];
    }
    float2 X[16];
    {
      const __half2* row = g_B + base + 65536;
#pragma unroll
      for (int n2 = 0; n2 < 16; n2++) X[n2] = __half22float2(row[lane + 16 * n2]);
      fft256g<1, false>(X, lane, tile + c * 273);
    }
    const float gn = ga[r];
#pragma unroll
    for (int k2 = 0; k2 < 8; k2++) {
      float sx = d0[k2] * Y0[k2].x + d1[k2] * Y0[k2].y + d2[k2] * X[k2].x + d3[k2] * X[k2].y;
      sx = fminf(fmaxf(sx * gn, -15.0f), 15.0f);
      float z = __expf(2.0f * sx);
      accv[k2] += __fdividef(z - 1.0f, z + 1.0f);
    }
  }
  float* dst = g_part + (size_t)rz * 262144 + bc * 32768;
#pragma unroll
  for (int k2 = 0; k2 < 8; k2++) {
    int n = bp + 256 * (lane + 16 * k2);
    dst[n] = accv[k2];
  }
}

// ---------------- K9: reduce 4 partials into output ----------------
__global__ void __launch_bounds__(256) k_reduce(float* __restrict__ out) {
  int i = blockIdx.x * 256 + threadIdx.x;  // 262144
  out[i] = g_part[i] + g_part[262144 + i] + g_part[524288 + i] + g_part[786432 + i];
}

extern "C" void kernel_launch(void* const* d_in, const int* in_sizes, int n_in,
                              void* d_out, int out_size) {
  const float* cs     = (const float*)d_in[0];
  const float* defs   = (const float*)d_in[1];
  const float* router = (const float*)d_in[2];
  const float* amp    = (const float*)d_in[3];
  const float* phase  = (const float*)d_in[4];
  const float* decay  = (const float*)d_in[5];
  const float* gains  = (const float*)d_in[6];
  float* out = (float*)d_out;

  k_routed<<<128, 256>>>(cs, router, out);
  k_dw<<<4, 256>>>(defs);
  k_spec0<<<dim3(5, 128), 256>>>(amp, phase, decay);
  k_frames2<<<dim3(8, 128), 256>>>();
  k_oa<<<128, 1024>>>();
  k_p1_sig<<<dim3(16, 256), 256>>>();
  k_p1_res<<<dim3(16, 128), 256>>>();
  k_fused3<<<dim3(16, 32), 256>>>();
  k_invfinal<<<dim3(16, 8, 4), 256>>>(gains);
  k_reduce<<<1024, 256>>>(out);
}

// round 6
// speedup vs baseline: 5.9516x; 1.2275x over previous
#include <cuda_runtime.h>
#include <cuda_fp16.h>
#include <math.h>

#define PI_F   3.14159265358979323846f
#define TWOPI_F 6.2831853071795864769f

// ---------------- static device scratch ----------------
__device__ float   g_routed[256 * 128];
__device__ float   g_dw[8 * 4 * 128];
__device__ float   g_invnorm[128];
__device__ float2  g_spec0[128 * 1025];      // per-bin frame-0 spectrum (av*dc*e^{i ph})
__device__ float2  g_ldc2[128 * 1025];       // (log dc, dc)
__device__ float   g_frames[128 * 32 * 2048];
__device__ float   g_res[128 * 32768];
__device__ __half2 g_Fsig[16777216];         // 256 x 65536  (pass1 output, fp16)
__device__ float2  g_Fres[8388608];          // 128 x 65536  (pass1 -> in-place pass2 in k_fused3)
__device__ __half2 g_B[33554432];            // 512 x 65536  (inverse pass1, pre-scaled, fp16)
__device__ float   g_part[4 * 262144];       // partial r-chunk sums

__device__ __forceinline__ float2 cmul(float2 a, float2 b) {
  return make_float2(a.x * b.x - a.y * b.y, a.x * b.y + a.y * b.x);
}
__device__ __forceinline__ unsigned rotl32(unsigned x, int r) {
  return (x << r) | (x >> (32 - r));
}

// JAX threefry2x32, partitionable 32-bit path: key=(0,123), count hi=0, lo=idx,
// bits = out0 ^ out1 -> uniform [-1,1).
__device__ __forceinline__ float noise_pm1(unsigned idx) {
  const unsigned ks0 = 0u, ks1 = 123u;
  const unsigned ks2 = ks0 ^ ks1 ^ 0x1BD11BDAu;
  unsigned x0 = ks0;
  unsigned x1 = idx + ks1;
#define TFR(r) { x0 += x1; x1 = rotl32(x1, r); x1 ^= x0; }
  TFR(13) TFR(15) TFR(26) TFR(6)
  x0 += ks1; x1 += ks2 + 1u;
  TFR(17) TFR(29) TFR(16) TFR(24)
  x0 += ks2; x1 += ks0 + 2u;
  TFR(13) TFR(15) TFR(26) TFR(6)
  x0 += ks0; x1 += ks1 + 3u;
  TFR(17) TFR(29) TFR(16) TFR(24)
  x0 += ks1; x1 += ks2 + 4u;
  TFR(13) TFR(15) TFR(26) TFR(6)
  x0 += ks2; x1 += ks0 + 5u;
#undef TFR
  unsigned bits = x0 ^ x1;
  float f = __uint_as_float((bits >> 9) | 0x3f800000u) - 1.0f;
  return f * 2.0f - 1.0f;
}

// ---------------- register DFT-16 (input bit-reversed, output natural) ----------------
template <int S>
__device__ __forceinline__ void fft16r(float2* r) {
  const float C1 = 0.9238795325112867f, S1 = 0.3826834323650898f, R2 = 0.7071067811865476f;
  const float sg = (float)S;
#define BF0(i0,i1) { float ax=r[i0].x, ay=r[i0].y, bx=r[i1].x, by=r[i1].y; \
  r[i0]=make_float2(ax+bx,ay+by); r[i1]=make_float2(ax-bx,ay-by); }
#define BFI(i0,i1) { float ax=r[i0].x, ay=r[i0].y, bx=r[i1].x, by=r[i1].y; \
  float tx=-sg*by, ty=sg*bx; \
  r[i0]=make_float2(ax+tx,ay+ty); r[i1]=make_float2(ax-tx,ay-ty); }
#define BFW(i0,i1,wr,wi) { float ax=r[i0].x, ay=r[i0].y, bx=r[i1].x, by=r[i1].y; \
  float tx=(wr)*bx-(wi)*by, ty=(wr)*by+(wi)*bx; \
  r[i0]=make_float2(ax+tx,ay+ty); r[i1]=make_float2(ax-tx,ay-ty); }
  BF0(0,1) BF0(2,3) BF0(4,5) BF0(6,7) BF0(8,9) BF0(10,11) BF0(12,13) BF0(14,15)
  BF0(0,2) BFI(1,3) BF0(4,6) BFI(5,7) BF0(8,10) BFI(9,11) BF0(12,14) BFI(13,15)
  BF0(0,4) BFW(1,5, R2, sg*R2) BFI(2,6) BFW(3,7, -R2, sg*R2)
  BF0(8,12) BFW(9,13, R2, sg*R2) BFI(10,14) BFW(11,15, -R2, sg*R2)
  BF0(0,8) BFW(1,9, C1, sg*S1) BFW(2,10, R2, sg*R2) BFW(3,11, S1, sg*C1)
  BFI(4,12) BFW(5,13, -S1, sg*C1) BFW(6,14, -R2, sg*R2) BFW(7,15, -C1, sg*S1)
#undef BF0
#undef BFI
#undef BFW
}

// ---------------- register DFT-8 (input bit-reversed, output natural) ----------------
template <int S>
__device__ __forceinline__ void fft8r(float2* r) {
  const float R2 = 0.7071067811865476f;
  const float sg = (float)S;
#define BF0(i0,i1) { float ax=r[i0].x, ay=r[i0].y, bx=r[i1].x, by=r[i1].y; \
  r[i0]=make_float2(ax+bx,ay+by); r[i1]=make_float2(ax-bx,ay-by); }
#define BFI(i0,i1) { float ax=r[i0].x, ay=r[i0].y, bx=r[i1].x, by=r[i1].y; \
  float tx=-sg*by, ty=sg*bx; \
  r[i0]=make_float2(ax+tx,ay+ty); r[i1]=make_float2(ax-tx,ay-ty); }
#define BFW(i0,i1,wr,wi) { float ax=r[i0].x, ay=r[i0].y, bx=r[i1].x, by=r[i1].y; \
  float tx=(wr)*bx-(wi)*by, ty=(wr)*by+(wi)*bx; \
  r[i0]=make_float2(ax+tx,ay+ty); r[i1]=make_float2(ax-tx,ay-ty); }
  BF0(0,1) BF0(2,3) BF0(4,5) BF0(6,7)
  BF0(0,2) BFI(1,3) BF0(4,6) BFI(5,7)
  BF0(0,4) BFW(1,5, R2, sg*R2) BFI(2,6) BFW(3,7, -R2, sg*R2)
#undef BF0
#undef BFI
#undef BFW
}

// Fill the 256-entry forward twiddle table T16[k1*16+lane] = e^{-2pi i k1*lane/256}.
// Call with >=256 threads; caller must __syncthreads() after.
__device__ __forceinline__ void fill_T16(float2* T16, int tid) {
  if (tid < 256) {
    float sv, cv;
    __sincosf(-(TWOPI_F / 256.0f) * (float)((tid >> 4) * (tid & 15)), &sv, &cv);
    T16[tid] = make_float2(cv, sv);
  }
}

// FFT-256 on 16 threads x 16 regs. Input x[n2] = v[lane + 16*n2] (natural),
// output x[k2] = V[lane + 16*k2]. tileC >= 16*17 float2 per group.
// T16: shared fwd twiddle table (conjugated on the fly for S=+1).
template <int S, bool BS>
__device__ __forceinline__ void fft256g(float2* x, int lane, float2* tileC,
                                        const float2* T16) {
  const int BR0=0,BR1=8,BR2=4,BR3=12,BR4=2,BR5=10,BR6=6,BR7=14,
            BR8=1,BR9=9,BR10=5,BR11=13,BR12=3,BR13=11,BR14=7,BR15=15;
  float2 q[16];
  q[0]=x[BR0]; q[1]=x[BR1]; q[2]=x[BR2]; q[3]=x[BR3];
  q[4]=x[BR4]; q[5]=x[BR5]; q[6]=x[BR6]; q[7]=x[BR7];
  q[8]=x[BR8]; q[9]=x[BR9]; q[10]=x[BR10]; q[11]=x[BR11];
  q[12]=x[BR12]; q[13]=x[BR13]; q[14]=x[BR14]; q[15]=x[BR15];
  fft16r<S>(q);
  if (BS) __syncthreads(); else __syncwarp();
#pragma unroll
  for (int k1 = 0; k1 < 16; k1++) {
    float2 w = T16[k1 * 16 + lane];
    if (S > 0) w.y = -w.y;
    tileC[k1 * 17 + lane] = cmul(q[k1], w);
  }
  if (BS) __syncthreads(); else __syncwarp();
  q[0]=tileC[lane*17+BR0]; q[1]=tileC[lane*17+BR1]; q[2]=tileC[lane*17+BR2]; q[3]=tileC[lane*17+BR3];
  q[4]=tileC[lane*17+BR4]; q[5]=tileC[lane*17+BR5]; q[6]=tileC[lane*17+BR6]; q[7]=tileC[lane*17+BR7];
  q[8]=tileC[lane*17+BR8]; q[9]=tileC[lane*17+BR9]; q[10]=tileC[lane*17+BR10]; q[11]=tileC[lane*17+BR11];
  q[12]=tileC[lane*17+BR12]; q[13]=tileC[lane*17+BR13]; q[14]=tileC[lane*17+BR14]; q[15]=tileC[lane*17+BR15];
  fft16r<S>(q);
#pragma unroll
  for (int i = 0; i < 16; i++) x[i] = q[i];
}

// Build 4 independent twiddle chains c[j] = w0 * s1^(4j), for interleaved
// advance-by-s1 loops (dependency depth ~6 instead of 16).
__device__ __forceinline__ void chain4(float2 w0, float2 s1, float2* c) {
  float2 s2 = cmul(s1, s1);
  float2 s4 = cmul(s2, s2);
  c[0] = w0;
  c[1] = cmul(w0, s4);
  c[2] = cmul(c[1], s4);
  c[3] = cmul(c[2], s4);
}

// ---------------- K1: routing einsum + before_upsample ----------------
__global__ void __launch_bounds__(256) k_routed(const float* __restrict__ cs,
                                                const float* __restrict__ router,
                                                float* __restrict__ out) {
  int i = blockIdx.x * 256 + threadIdx.x;
  int f = i & 127, r = (i >> 7) & 31, bc = i >> 12;
  float acc = 0.0f;
#pragma unroll
  for (int c = 0; c < 16; c++)
    acc += cs[(bc * 16 + c) * 128 + f] * router[c * 32 + r];
  g_routed[i] = acc;
  out[262144 + i] = acc;
}

// ---------------- K1b: deformation softmax ----------------
__global__ void __launch_bounds__(256) k_dw(const float* __restrict__ defs) {
  int i = blockIdx.x * 256 + threadIdx.x;
  if (i >= 1024) return;
  int f = i & 127, bc = i >> 7;
  float v[4], mx = -1e30f;
#pragma unroll
  for (int e = 0; e < 4; e++) {
    float x = defs[(bc * 4 + e) * 128 + f] + (e == 0 ? 1.0f : 0.0f);
    v[e] = x; mx = fmaxf(mx, x);
  }
  float s = 0.0f;
#pragma unroll
  for (int e = 0; e < 4; e++) { v[e] = expf(v[e] - mx); s += v[e]; }
  float inv = 1.0f / s;
#pragma unroll
  for (int e = 0; e < 4; e++) g_dw[bc * 512 + e * 128 + f] = v[e] * inv;
}

// ---------------- K2a: per-bin spectral precompute ----------------
__global__ void __launch_bounds__(256) k_spec0(const float* __restrict__ amp,
                                               const float* __restrict__ phase,
                                               const float* __restrict__ decay) {
  int k = blockIdx.x * 256 + threadIdx.x;
  if (k >= 1025) return;
  int re = blockIdx.y;
  int r = re >> 2, e = re & 3;
  int base = (r * 1025 + k) * 4 + e;
  float av = fabsf(amp[base]);
  float dc = 0.5f + 0.45f / (1.0f + expf(-decay[base]));
  float dcv = dc + 1e-12f;
  float ldc = logf(dcv);
  float ph = tanhf(phase[base]) * PI_F;
  float sv, cv; sincosf(ph, &sv, &cv);
  g_spec0[re * 1025 + k] = make_float2(av * dcv * cv, av * dcv * sv);
  g_ldc2[re * 1025 + k]  = make_float2(ldc, dcv);
}

// ---------------- K2b: paired irfft(2048)*hann via register FFT ----------------
__global__ void __launch_bounds__(256) k_frames2() {
  __shared__ float2 SM[4640];
  __shared__ float2 T16[256];
  const int tid = threadIdx.x;
  fill_T16(T16, tid);
  const int sub = tid >> 7, lt = tid & 127;
  const int g = lt >> 4, gl = lt & 15;
  const int re = blockIdx.y;
  const int p = blockIdx.x * 2 + sub;
  const int f0 = 2 * p;
  const float2* sp0 = g_spec0 + re * 1025;
  const float2* sl  = g_ldc2  + re * 1025;
  float2 X[16];
#pragma unroll
  for (int n2 = 0; n2 < 16; n2++) {
    int n = 8 * (gl + 16 * n2) + g;
    int mir = n > 1024;
    int k = mir ? 2048 - n : n;
    float2 c0 = sp0[k];
    float2 ld = sl[k];
    float e0 = __expf((float)f0 * ld.x);
    float sx = c0.x * e0;
    float sy = (mir ? -c0.y : c0.y) * e0;
    if (n == 0 || n == 1024) sy = 0.0f;
    X[n2] = make_float2(sx - sy * ld.y, sy + sx * ld.y);
  }
  __syncthreads();   // T16 ready
  fft256g<1, false>(X, gl, SM + (sub * 8 + g) * 273, T16);
  __syncthreads();
  {
    float sv, cv;
    __sincosf((TWOPI_F / 2048.0f) * (float)(g * gl), &sv, &cv);
    float2 w0 = make_float2(cv, sv);
    __sincosf((TWOPI_F / 2048.0f) * (float)(g * 16), &sv, &cv);
    float2 s1 = make_float2(cv, sv);
    float2 cc[4];
    chain4(w0, s1, cc);
    float2* tp = SM + sub * 2320;
#pragma unroll
    for (int t = 0; t < 4; t++) {
#pragma unroll
      for (int j = 0; j < 4; j++) {
        int k2 = 4 * j + t;
        int k1 = gl + 16 * k2;
        tp[k1 * 9 + g] = cmul(X[k2], cc[j]);
        cc[j] = cmul(cc[j], s1);
      }
    }
  }
  __syncthreads();
  const float2* tp = SM + sub * 2320;
  float* fa = g_frames + ((size_t)re * 32 + f0) * 2048;
  float* fb = fa + 2048;
#pragma unroll
  for (int h = 0; h < 2; h++) {
    int k1 = lt + 128 * h;
    float2 q[8];
    q[0] = tp[k1 * 9 + 0]; q[1] = tp[k1 * 9 + 4];
    q[2] = tp[k1 * 9 + 2]; q[3] = tp[k1 * 9 + 6];
    q[4] = tp[k1 * 9 + 1]; q[5] = tp[k1 * 9 + 5];
    q[6] = tp[k1 * 9 + 3]; q[7] = tp[k1 * 9 + 7];
    fft8r<1>(q);
#pragma unroll
    for (int k2 = 0; k2 < 8; k2++) {
      int t = k1 + 256 * k2;
      float sc = (0.5f - 0.5f * __cosf((TWOPI_F / 2048.0f) * (float)t)) * (1.0f / 2048.0f);
      fa[t] = q[k2].x * sc;
      fb[t] = q[k2].y * sc;
    }
  }
}

// ---------------- K3: overlap-add + inv-norm ----------------
__global__ void __launch_bounds__(1024) k_oa() {
  const int re = blockIdx.x, tid = threadIdx.x;
  const float* F = g_frames + (size_t)re * 32 * 2048;
  float* R = g_res + (size_t)re * 32768;
  float ss = 0.0f;
#pragma unroll
  for (int f = 0; f < 32; f++) {
    float v = F[f * 2048 + tid];
    if (f > 0) v += F[(f - 1) * 2048 + 1024 + tid];
    R[f * 1024 + tid] = v;
    ss += v * v;
  }
#pragma unroll
  for (int o = 16; o > 0; o >>= 1) ss += __shfl_xor_sync(0xffffffffu, ss, o);
  __shared__ float red[32];
  if ((tid & 31) == 0) red[tid >> 5] = ss;
  __syncthreads();
  if (tid < 32) {
    float v = red[tid];
#pragma unroll
    for (int o = 16; o > 0; o >>= 1) v += __shfl_xor_sync(0xffffffffu, v, o);
    if (tid == 0) g_invnorm[re] = 1.0f / (sqrtf(v) + 1e-8f);
  }
}

// ---------------- K4: pass1 columns, signal (fused upsample*noise) ----------------
__global__ void __launch_bounds__(256) k_p1_sig() {
  __shared__ float2 tile[16 * 273];
  __shared__ float2 T16[256];
  __shared__ float rrow[128];
  const int tid = threadIdx.x;
  fill_T16(T16, tid);
  const int lane = tid >> 4, c = tid & 15;
  const int s = blockIdx.y;
  const int b = blockIdx.x * 16 + c;
  if (tid < 128) rrow[tid] = g_routed[s * 128 + tid];
  __syncthreads();
  float2 X[16];
#pragma unroll
  for (int n2 = 0; n2 < 16; n2++) {
    float v = 0.0f;
    if (n2 < 8) {
      int j = lane + 16 * n2;
      int n = b + 256 * j;
      float pos = fminf(fmaxf((n + 0.5f) * (1.0f / 256.0f) - 0.5f, 0.0f), 127.0f);
      int lo = (int)pos;
      int hi = min(lo + 1, 127);
      float w = pos - (float)lo;
      v = (rrow[lo] * (1.0f - w) + rrow[hi] * w) * noise_pm1((unsigned)(s * 32768 + n));
    }
    X[n2] = make_float2(v, 0.0f);
  }
  fft256g<-1, true>(X, lane, tile + c * 273, T16);
  float sv, cv;
  __sincosf(-(TWOPI_F / 65536.0f) * (float)(lane * b), &sv, &cv);
  float2 w0 = make_float2(cv, sv);
  __sincosf(-(TWOPI_F / 65536.0f) * (float)(16 * b), &sv, &cv);
  float2 s1 = make_float2(cv, sv);
  float2 cc[4];
  chain4(w0, s1, cc);
  __half2* dst = g_Fsig + (size_t)s * 65536 + b;
#pragma unroll
  for (int t = 0; t < 4; t++) {
#pragma unroll
    for (int j = 0; j < 4; j++) {
      int k2 = 4 * j + t;
      float2 z = cmul(X[k2], cc[j]);
      dst[(lane + 16 * k2) * 256] = __floats2half2_rn(z.x, z.y);
      cc[j] = cmul(cc[j], s1);
    }
  }
}

// ---------------- K5: pass1 columns, resonances ----------------
__global__ void __launch_bounds__(256) k_p1_res() {
  __shared__ float2 tile[16 * 273];
  __shared__ float2 T16[256];
  const int tid = threadIdx.x;
  fill_T16(T16, tid);
  const int lane = tid >> 4, c = tid & 15;
  const int re = blockIdx.y;
  const int b = blockIdx.x * 16 + c;
  const float inv = g_invnorm[re];
  float2 X[16];
#pragma unroll
  for (int n2 = 0; n2 < 16; n2++) {
    float v = 0.0f;
    if (n2 < 8) v = g_res[(size_t)re * 32768 + b + 256 * (lane + 16 * n2)] * inv;
    X[n2] = make_float2(v, 0.0f);
  }
  __syncthreads();   // T16 ready
  fft256g<-1, true>(X, lane, tile + c * 273, T16);
  float sv, cv;
  __sincosf(-(TWOPI_F / 65536.0f) * (float)(lane * b), &sv, &cv);
  float2 w0 = make_float2(cv, sv);
  __sincosf(-(TWOPI_F / 65536.0f) * (float)(16 * b), &sv, &cv);
  float2 s1 = make_float2(cv, sv);
  float2 cc[4];
  chain4(w0, s1, cc);
  float2* dst = g_Fres + (size_t)re * 65536 + b;
#pragma unroll
  for (int t = 0; t < 4; t++) {
#pragma unroll
    for (int j = 0; j < 4; j++) {
      int k2 = 4 * j + t;
      dst[(lane + 16 * k2) * 256] = cmul(X[k2], cc[j]);
      cc[j] = cmul(cc[j], s1);
    }
  }
}

// ---------------- K7: fused res-pass2 + fwd pass2(sig) + product + inverse pass1 ----------------
__global__ void __launch_bounds__(256) k_fused3() {
  __shared__ float2 tile[16 * 273];
  __shared__ float2 T16[256];
  const int tid = threadIdx.x;
  fill_T16(T16, tid);
  const int c = tid >> 4, lane = tid & 15;
  const int r = blockIdx.y;
  const int d = blockIdx.x * 16 + c;
  __syncthreads();   // T16 ready
  // --- inline res pass2 for this block's rows (thread-private RAW only) ---
#pragma unroll
  for (int re4 = 0; re4 < 4; re4++) {
    float2* row = g_Fres + (size_t)(r * 4 + re4) * 65536 + d * 256;
    float2 X[16];
#pragma unroll
    for (int n2 = 0; n2 < 16; n2++) X[n2] = row[lane + 16 * n2];
    fft256g<-1, false>(X, lane, tile + c * 273, T16);
#pragma unroll
    for (int k2 = 0; k2 < 16; k2++) row[lane + 16 * k2] = X[k2];
  }
  __syncwarp();
  for (int bc = 0; bc < 8; bc++) {
    const int s = bc * 32 + r;
    const __half2* srow = g_Fsig + (size_t)s * 65536 + d * 256;
    float2 X[16];
#pragma unroll
    for (int n2 = 0; n2 < 16; n2++) X[n2] = __half22float2(srow[lane + 16 * n2]);
    fft256g<-1, false>(X, lane, tile + c * 273, T16);
#pragma unroll
    for (int hb = 0; hb < 2; hb++) {
      const float2* f0 = g_Fres + (size_t)(r * 4 + 2 * hb) * 65536 + d * 256;
      const float2* f1 = f0 + 65536;
      float2 Y[16];
#pragma unroll
      for (int k = 0; k < 16; k++) {
        int e = lane + 16 * k;
        float2 a = X[k];
        float2 p0 = cmul(a, f0[e]);
        float2 p1 = cmul(a, f1[e]);
        Y[k] = make_float2(p0.x - p1.y, p0.y + p1.x);   // p0 + i*p1
      }
      fft256g<1, false>(Y, lane, tile + c * 273, T16);
      float sv, cv;
      __sincosf((TWOPI_F / 65536.0f) * (float)(lane * d), &sv, &cv);
      const float scl = 1.0f / 65536.0f;
      float2 w0 = make_float2(cv * scl, sv * scl);
      __sincosf((TWOPI_F / 65536.0f) * (float)(16 * d), &sv, &cv);
      float2 s1 = make_float2(cv, sv);
      float2 cc[4];
      chain4(w0, s1, cc);
      float2* st = tile + c * 273;
      __syncwarp();
#pragma unroll
      for (int t = 0; t < 4; t++) {
#pragma unroll
        for (int j = 0; j < 4; j++) {
          int k2 = 4 * j + t;
          st[lane + 16 * k2] = cmul(Y[k2], cc[j]);
          cc[j] = cmul(cc[j], s1);
        }
      }
      __syncthreads();
      const int oc = tid & 15, jb = tid >> 4;
      __half2* dst = g_B + ((size_t)(s * 2 + hb)) * 65536 + blockIdx.x * 16 + oc;
      const float2* sr2 = tile + oc * 273;
#pragma unroll
      for (int m = 0; m < 16; m++) {
        float2 z = sr2[jb + 16 * m];
        dst[(jb + 16 * m) * 256] = __floats2half2_rn(z.x, z.y);
      }
      __syncthreads();
    }
  }
}

// ---------------- K8: fused inverse pass2 + deformation mix + tanh (partial r-sum) ----------------
__global__ void __launch_bounds__(256) k_invfinal(const float* __restrict__ gains) {
  __shared__ float2 tile[16 * 273];
  __shared__ float2 T16[256];
  __shared__ float dw[512];
  __shared__ float ga[32];
  const int tid = threadIdx.x;
  fill_T16(T16, tid);
  const int c = tid >> 4, lane = tid & 15;
  const int bc = blockIdx.y, rz = blockIdx.z;
  const int bp = blockIdx.x * 16 + c;
  for (int i = tid; i < 512; i += 256) dw[i] = g_dw[bc * 512 + i];
  if (tid < 32) ga[tid] = fabsf(gains[tid]);
  __syncthreads();
  float d0[8], d1[8], d2[8], d3[8], accv[8];
#pragma unroll
  for (int k2 = 0; k2 < 8; k2++) {
    int n = bp + 256 * (lane + 16 * k2);
    float pos = fminf(fmaxf((n + 0.5f) * (1.0f / 256.0f) - 0.5f, 0.0f), 127.0f);
    int lo = (int)pos;
    int hi = min(lo + 1, 127);
    float w = pos - (float)lo;
    d0[k2] = dw[lo]       * (1.0f - w) + dw[hi]       * w;
    d1[k2] = dw[128 + lo] * (1.0f - w) + dw[128 + hi] * w;
    d2[k2] = dw[256 + lo] * (1.0f - w) + dw[256 + hi] * w;
    d3[k2] = dw[384 + lo] * (1.0f - w) + dw[384 + hi] * w;
    accv[k2] = 0.0f;
  }
  for (int rr = 0; rr < 8; rr++) {
    const int r = rz * 8 + rr;
    const size_t base = ((size_t)((bc * 32 + r) * 2)) * 65536 + (size_t)bp * 256;
    float2 Y0[8];
    {
      const __half2* row = g_B + base;
      float2 X[16];
#pragma unroll
      for (int n2 = 0; n2 < 16; n2++) X[n2] = __half22float2(row[lane + 16 * n2]);
      fft256g<1, false>(X, lane, tile + c * 273, T16);
#pragma unroll
      for (int k2 = 0; k2 < 8; k2++) Y0[k2] = X[k2];
    }
    float2 X[16];
    {
      const __half2* row = g_B + base + 65536;
#pragma unroll
      for (int n2 = 0; n2 < 16; n2++) X[n2] = __half22float2(row[lane + 16 * n2]);
      fft256g<1, false>(X, lane, tile + c * 273, T16);
    }
    const float gn = ga[r];
#pragma unroll
    for (int k2 = 0; k2 < 8; k2++) {
      float sx = d0[k2] * Y0[k2].x + d1[k2] * Y0[k2].y + d2[k2] * X[k2].x + d3[k2] * X[k2].y;
      sx = fminf(fmaxf(sx * gn, -15.0f), 15.0f);
      float z = __expf(2.0f * sx);
      accv[k2] += __fdividef(z - 1.0f, z + 1.0f);
    }
  }
  float* dst = g_part + (size_t)rz * 262144 + bc * 32768;
#pragma unroll
  for (int k2 = 0; k2 < 8; k2++) {
    int n = bp + 256 * (lane + 16 * k2);
    dst[n] = accv[k2];
  }
}

// ---------------- K9: reduce 4 partials into output ----------------
__global__ void __launch_bounds__(256) k_reduce(float* __restrict__ out) {
  int i = blockIdx.x * 256 + threadIdx.x;  // 262144
  out[i] = g_part[i] + g_part[262144 + i] + g_part[524288 + i] + g_part[786432 + i];
}

extern "C" void kernel_launch(void* const* d_in, const int* in_sizes, int n_in,
                              void* d_out, int out_size) {
  const float* cs     = (const float*)d_in[0];
  const float* defs   = (const float*)d_in[1];
  const float* router = (const float*)d_in[2];
  const float* amp    = (const float*)d_in[3];
  const float* phase  = (const float*)d_in[4];
  const float* decay  = (const float*)d_in[5];
  const float* gains  = (const float*)d_in[6];
  float* out = (float*)d_out;

  k_routed<<<128, 256>>>(cs, router, out);
  k_dw<<<4, 256>>>(defs);
  k_spec0<<<dim3(5, 128), 256>>>(amp, phase, decay);
  k_frames2<<<dim3(8, 128), 256>>>();
  k_oa<<<128, 1024>>>();
  k_p1_sig<<<dim3(16, 256), 256>>>();
  k_p1_res<<<dim3(16, 128), 256>>>();
  k_fused3<<<dim3(16, 32), 256>>>();
  k_invfinal<<<dim3(16, 8, 4), 256>>>(gains);
  k_reduce<<<1024, 256>>>(out);
}

// round 7
// speedup vs baseline: 6.1031x; 1.0255x over previous
#include <cuda_runtime.h>
#include <cuda_fp16.h>
#include <math.h>

#define PI_F   3.14159265358979323846f
#define TWOPI_F 6.2831853071795864769f

typedef unsigned long long ull;

// ---------------- static device scratch ----------------
__device__ float   g_routed[256 * 128];
__device__ float   g_dw[8 * 4 * 128];
__device__ float   g_invnorm[128];
__device__ float2  g_spec0[128 * 1025];      // per-bin frame-0 spectrum (av*dc*e^{i ph})
__device__ float2  g_ldc2[128 * 1025];       // (log dc, dc)
__device__ float   g_frames[128 * 32 * 2048];
__device__ __half2 g_Fsig[16777216];         // 256 x 65536  (pass1 output, fp16)
__device__ float2  g_Fres[8388608];          // 128 x 65536  (pass1 -> in-place pass2 in k_fused3)
__device__ __half2 g_B[33554432];            // 512 x 65536  (inverse pass1, pre-scaled, fp16)
__device__ float   g_part[4 * 262144];       // partial r-chunk sums

__device__ __forceinline__ float2 cmul(float2 a, float2 b) {
  return make_float2(a.x * b.x - a.y * b.y, a.x * b.y + a.y * b.x);
}
__device__ __forceinline__ unsigned rotl32(unsigned x, int r) {
  return (x << r) | (x >> (32 - r));
}
__device__ __forceinline__ ull f2u(float2 v) {
  ull r;
  asm("mov.b64 %0, {%1, %2};" : "=l"(r) : "f"(v.x), "f"(v.y));
  return r;
}
__device__ __forceinline__ float2 u2f(ull u) {
  float2 v;
  asm("mov.b64 {%0, %1}, %2;" : "=f"(v.x), "=f"(v.y) : "l"(u));
  return v;
}

// JAX threefry2x32, partitionable 32-bit path: key=(0,123), count hi=0, lo=idx,
// bits = out0 ^ out1 -> uniform [-1,1).
__device__ __forceinline__ float noise_pm1(unsigned idx) {
  const unsigned ks0 = 0u, ks1 = 123u;
  const unsigned ks2 = ks0 ^ ks1 ^ 0x1BD11BDAu;
  unsigned x0 = ks0;
  unsigned x1 = idx + ks1;
#define TFR(r) { x0 += x1; x1 = rotl32(x1, r); x1 ^= x0; }
  TFR(13) TFR(15) TFR(26) TFR(6)
  x0 += ks1; x1 += ks2 + 1u;
  TFR(17) TFR(29) TFR(16) TFR(24)
  x0 += ks2; x1 += ks0 + 2u;
  TFR(13) TFR(15) TFR(26) TFR(6)
  x0 += ks0; x1 += ks1 + 3u;
  TFR(17) TFR(29) TFR(16) TFR(24)
  x0 += ks1; x1 += ks2 + 4u;
  TFR(13) TFR(15) TFR(26) TFR(6)
  x0 += ks2; x1 += ks0 + 5u;
#undef TFR
  unsigned bits = x0 ^ x1;
  float f = __uint_as_float((bits >> 9) | 0x3f800000u) - 1.0f;
  return f * 2.0f - 1.0f;
}

// ---------------- packed (f32x2) DFT-16, input bit-reversed, output natural ----------------
// Each ull is a packed complex (re = lo lane, im = hi lane). Same rounding as
// scalar mul/fma sequence: PSUB(d,a,b) = fma(b, -1, a) == a-b exactly.
#define PADD(d,a,b)   asm("add.rn.f32x2 %0,%1,%2;"    : "=l"(d) : "l"(a), "l"(b))
#define PSUB(d,a,b)   asm("fma.rn.f32x2 %0,%1,%2,%3;" : "=l"(d) : "l"(b), "l"(PN1), "l"(a))
#define PMUL(d,a,b)   asm("mul.rn.f32x2 %0,%1,%2;"    : "=l"(d) : "l"(a), "l"(b))
#define PFMA(d,a,b,c) asm("fma.rn.f32x2 %0,%1,%2,%3;" : "=l"(d) : "l"(a), "l"(b), "l"(c))
// d = +i*b = (-b.im, b.re)
#define PROTP(d,b) asm("{.reg .f32 x,y,ny; mov.b64 {x,y},%1; neg.f32 ny,y; mov.b64 %0,{ny,x};}" : "=l"(d) : "l"(b))
// d = -i*b = (b.im, -b.re)
#define PROTN(d,b) asm("{.reg .f32 x,y,nx; mov.b64 {x,y},%1; neg.f32 nx,x; mov.b64 %0,{y,nx};}" : "=l"(d) : "l"(b))

template <int S>
__device__ __forceinline__ void fft16p(ull* r) {
  ull PN1, PR2, PC1, PS1;
  asm("mov.b64 %0,{%1,%1};" : "=l"(PN1) : "f"(-1.0f));
  asm("mov.b64 %0,{%1,%1};" : "=l"(PR2) : "f"(0.7071067811865476f));
  asm("mov.b64 %0,{%1,%1};" : "=l"(PC1) : "f"(0.9238795325112867f));
  asm("mov.b64 %0,{%1,%1};" : "=l"(PS1) : "f"(0.3826834323650898f));
#define BF0(i0,i1) { ull s_, d_; PADD(s_, r[i0], r[i1]); PSUB(d_, r[i0], r[i1]); r[i0]=s_; r[i1]=d_; }
#define BFI(i0,i1) { ull t_, s_, d_; if (S > 0) { PROTP(t_, r[i1]); } else { PROTN(t_, r[i1]); } \
  PADD(s_, r[i0], t_); PSUB(d_, r[i0], t_); r[i0]=s_; r[i1]=d_; }
// t' = (|wr| + i*(WINEG ? -|wi| : |wi|)) * b; WRNEG swaps the +/- outputs (w = -t' case)
#define BFW(i0,i1, PWR, WRNEG, PWI, WINEG) { ull rt_, tm_, t_, s_, d_; \
  if (WINEG) { PROTN(rt_, r[i1]); } else { PROTP(rt_, r[i1]); } \
  PMUL(tm_, PWR, r[i1]); \
  PFMA(t_, PWI, rt_, tm_); \
  if (WRNEG) { PSUB(s_, r[i0], t_); PADD(d_, r[i0], t_); } \
  else       { PADD(s_, r[i0], t_); PSUB(d_, r[i0], t_); } \
  r[i0]=s_; r[i1]=d_; }
  // stage 1
  BF0(0,1) BF0(2,3) BF0(4,5) BF0(6,7) BF0(8,9) BF0(10,11) BF0(12,13) BF0(14,15)
  // stage 2
  BF0(0,2) BFI(1,3) BF0(4,6) BFI(5,7) BF0(8,10) BFI(9,11) BF0(12,14) BFI(13,15)
  // stage 3: w = (R2, sg*R2) and (-R2, sg*R2)
  BF0(0,4)  BFW(1,5,  PR2, false, PR2, (S < 0)) BFI(2,6)   BFW(3,7,  PR2, true, PR2, (S > 0))
  BF0(8,12) BFW(9,13, PR2, false, PR2, (S < 0)) BFI(10,14) BFW(11,15,PR2, true, PR2, (S > 0))
  // stage 4
  BF0(0,8)
  BFW(1,9,  PC1, false, PS1, (S < 0))
  BFW(2,10, PR2, false, PR2, (S < 0))
  BFW(3,11, PS1, false, PC1, (S < 0))
  BFI(4,12)
  BFW(5,13, PS1, true,  PC1, (S > 0))
  BFW(6,14, PR2, true,  PR2, (S > 0))
  BFW(7,15, PC1, true,  PS1, (S > 0))
#undef BF0
#undef BFI
#undef BFW
}

// ---------------- register DFT-8 (scalar; only used in k_frames2) ----------------
template <int S>
__device__ __forceinline__ void fft8r(float2* r) {
  const float R2 = 0.7071067811865476f;
  const float sg = (float)S;
#define BF0(i0,i1) { float ax=r[i0].x, ay=r[i0].y, bx=r[i1].x, by=r[i1].y; \
  r[i0]=make_float2(ax+bx,ay+by); r[i1]=make_float2(ax-bx,ay-by); }
#define BFI(i0,i1) { float ax=r[i0].x, ay=r[i0].y, bx=r[i1].x, by=r[i1].y; \
  float tx=-sg*by, ty=sg*bx; \
  r[i0]=make_float2(ax+tx,ay+ty); r[i1]=make_float2(ax-tx,ay-ty); }
#define BFW(i0,i1,wr,wi) { float ax=r[i0].x, ay=r[i0].y, bx=r[i1].x, by=r[i1].y; \
  float tx=(wr)*bx-(wi)*by, ty=(wr)*by+(wi)*bx; \
  r[i0]=make_float2(ax+tx,ay+ty); r[i1]=make_float2(ax-tx,ay-ty); }
  BF0(0,1) BF0(2,3) BF0(4,5) BF0(6,7)
  BF0(0,2) BFI(1,3) BF0(4,6) BFI(5,7)
  BF0(0,4) BFW(1,5, R2, sg*R2) BFI(2,6) BFW(3,7, -R2, sg*R2)
#undef BF0
#undef BFI
#undef BFW
}

// Fill the 256-entry forward twiddle table T16[k1*16+lane] = e^{-2pi i k1*lane/256}.
__device__ __forceinline__ void fill_T16(float2* T16, int tid) {
  if (tid < 256) {
    float sv, cv;
    __sincosf(-(TWOPI_F / 256.0f) * (float)((tid >> 4) * (tid & 15)), &sv, &cv);
    T16[tid] = make_float2(cv, sv);
  }
}

// FFT-256 on 16 threads x 16 regs (packed core). Input x[n2] = v[lane+16*n2]
// (natural), output x[k2] = V[lane+16*k2]. tileC >= 16*17 float2 per group.
template <int S, bool BS>
__device__ __forceinline__ void fft256g(float2* x, int lane, float2* tileC,
                                        const float2* T16) {
  ull q[16];
  q[0]=f2u(x[0]);  q[1]=f2u(x[8]);  q[2]=f2u(x[4]);  q[3]=f2u(x[12]);
  q[4]=f2u(x[2]);  q[5]=f2u(x[10]); q[6]=f2u(x[6]);  q[7]=f2u(x[14]);
  q[8]=f2u(x[1]);  q[9]=f2u(x[9]);  q[10]=f2u(x[5]); q[11]=f2u(x[13]);
  q[12]=f2u(x[3]); q[13]=f2u(x[11]);q[14]=f2u(x[7]); q[15]=f2u(x[15]);
  fft16p<S>(q);
  if (BS) __syncthreads(); else __syncwarp();
#pragma unroll
  for (int k1 = 0; k1 < 16; k1++) {
    float2 w = T16[k1 * 16 + lane];
    if (S > 0) w.y = -w.y;
    tileC[k1 * 17 + lane] = cmul(u2f(q[k1]), w);
  }
  if (BS) __syncthreads(); else __syncwarp();
  q[0]=f2u(tileC[lane*17+0]);  q[1]=f2u(tileC[lane*17+8]);
  q[2]=f2u(tileC[lane*17+4]);  q[3]=f2u(tileC[lane*17+12]);
  q[4]=f2u(tileC[lane*17+2]);  q[5]=f2u(tileC[lane*17+10]);
  q[6]=f2u(tileC[lane*17+6]);  q[7]=f2u(tileC[lane*17+14]);
  q[8]=f2u(tileC[lane*17+1]);  q[9]=f2u(tileC[lane*17+9]);
  q[10]=f2u(tileC[lane*17+5]); q[11]=f2u(tileC[lane*17+13]);
  q[12]=f2u(tileC[lane*17+3]); q[13]=f2u(tileC[lane*17+11]);
  q[14]=f2u(tileC[lane*17+7]); q[15]=f2u(tileC[lane*17+15]);
  fft16p<S>(q);
#pragma unroll
  for (int i = 0; i < 16; i++) x[i] = u2f(q[i]);
}

// Build 4 independent twiddle chains c[j] = w0 * s1^(4j).
__device__ __forceinline__ void chain4(float2 w0, float2 s1, float2* c) {
  float2 s2 = cmul(s1, s1);
  float2 s4 = cmul(s2, s2);
  c[0] = w0;
  c[1] = cmul(w0, s4);
  c[2] = cmul(c[1], s4);
  c[3] = cmul(c[2], s4);
}

// ---------------- K1: routing einsum + before_upsample ----------------
__global__ void __launch_bounds__(256) k_routed(const float* __restrict__ cs,
                                                const float* __restrict__ router,
                                                float* __restrict__ out) {
  int i = blockIdx.x * 256 + threadIdx.x;
  int f = i & 127, r = (i >> 7) & 31, bc = i >> 12;
  float acc = 0.0f;
#pragma unroll
  for (int c = 0; c < 16; c++)
    acc += cs[(bc * 16 + c) * 128 + f] * router[c * 32 + r];
  g_routed[i] = acc;
  out[262144 + i] = acc;
}

// ---------------- K1b: deformation softmax ----------------
__global__ void __launch_bounds__(256) k_dw(const float* __restrict__ defs) {
  int i = blockIdx.x * 256 + threadIdx.x;
  if (i >= 1024) return;
  int f = i & 127, bc = i >> 7;
  float v[4], mx = -1e30f;
#pragma unroll
  for (int e = 0; e < 4; e++) {
    float x = defs[(bc * 4 + e) * 128 + f] + (e == 0 ? 1.0f : 0.0f);
    v[e] = x; mx = fmaxf(mx, x);
  }
  float s = 0.0f;
#pragma unroll
  for (int e = 0; e < 4; e++) { v[e] = expf(v[e] - mx); s += v[e]; }
  float inv = 1.0f / s;
#pragma unroll
  for (int e = 0; e < 4; e++) g_dw[bc * 512 + e * 128 + f] = v[e] * inv;
}

// ---------------- K2a: per-bin spectral precompute ----------------
__global__ void __launch_bounds__(256) k_spec0(const float* __restrict__ amp,
                                               const float* __restrict__ phase,
                                               const float* __restrict__ decay) {
  int k = blockIdx.x * 256 + threadIdx.x;
  if (k >= 1025) return;
  int re = blockIdx.y;
  int r = re >> 2, e = re & 3;
  int base = (r * 1025 + k) * 4 + e;
  float av = fabsf(amp[base]);
  float dc = 0.5f + 0.45f / (1.0f + expf(-decay[base]));
  float dcv = dc + 1e-12f;
  float ldc = logf(dcv);
  float ph = tanhf(phase[base]) * PI_F;
  float sv, cv; sincosf(ph, &sv, &cv);
  g_spec0[re * 1025 + k] = make_float2(av * dcv * cv, av * dcv * sv);
  g_ldc2[re * 1025 + k]  = make_float2(ldc, dcv);
}

// ---------------- K2b: paired irfft(2048)*hann via register FFT ----------------
__global__ void __launch_bounds__(256) k_frames2() {
  __shared__ float2 SM[4640];
  __shared__ float2 T16[256];
  const int tid = threadIdx.x;
  fill_T16(T16, tid);
  const int sub = tid >> 7, lt = tid & 127;
  const int g = lt >> 4, gl = lt & 15;
  const int re = blockIdx.y;
  const int p = blockIdx.x * 2 + sub;
  const int f0 = 2 * p;
  const float2* sp0 = g_spec0 + re * 1025;
  const float2* sl  = g_ldc2  + re * 1025;
  float2 X[16];
#pragma unroll
  for (int n2 = 0; n2 < 16; n2++) {
    int n = 8 * (gl + 16 * n2) + g;
    int mir = n > 1024;
    int k = mir ? 2048 - n : n;
    float2 c0 = sp0[k];
    float2 ld = sl[k];
    float e0 = __expf((float)f0 * ld.x);
    float sx = c0.x * e0;
    float sy = (mir ? -c0.y : c0.y) * e0;
    if (n == 0 || n == 1024) sy = 0.0f;
    X[n2] = make_float2(sx - sy * ld.y, sy + sx * ld.y);
  }
  __syncthreads();   // T16 ready
  fft256g<1, false>(X, gl, SM + (sub * 8 + g) * 273, T16);
  __syncthreads();
  {
    float sv, cv;
    __sincosf((TWOPI_F / 2048.0f) * (float)(g * gl), &sv, &cv);
    float2 w0 = make_float2(cv, sv);
    __sincosf((TWOPI_F / 2048.0f) * (float)(g * 16), &sv, &cv);
    float2 s1 = make_float2(cv, sv);
    float2 cc[4];
    chain4(w0, s1, cc);
    float2* tp = SM + sub * 2320;
#pragma unroll
    for (int t = 0; t < 4; t++) {
#pragma unroll
      for (int j = 0; j < 4; j++) {
        int k2 = 4 * j + t;
        int k1 = gl + 16 * k2;
        tp[k1 * 9 + g] = cmul(X[k2], cc[j]);
        cc[j] = cmul(cc[j], s1);
      }
    }
  }
  __syncthreads();
  const float2* tp = SM + sub * 2320;
  float* fa = g_frames + ((size_t)re * 32 + f0) * 2048;
  float* fb = fa + 2048;
#pragma unroll
  for (int h = 0; h < 2; h++) {
    int k1 = lt + 128 * h;
    float2 q[8];
    q[0] = tp[k1 * 9 + 0]; q[1] = tp[k1 * 9 + 4];
    q[2] = tp[k1 * 9 + 2]; q[3] = tp[k1 * 9 + 6];
    q[4] = tp[k1 * 9 + 1]; q[5] = tp[k1 * 9 + 5];
    q[6] = tp[k1 * 9 + 3]; q[7] = tp[k1 * 9 + 7];
    fft8r<1>(q);
#pragma unroll
    for (int k2 = 0; k2 < 8; k2++) {
      int t = k1 + 256 * k2;
      float sc = (0.5f - 0.5f * __cosf((TWOPI_F / 2048.0f) * (float)t)) * (1.0f / 2048.0f);
      fa[t] = q[k2].x * sc;
      fb[t] = q[k2].y * sc;
    }
  }
}

// ---------------- K3: inv-norm only (OLA folded into k_p1_res) ----------------
__global__ void __launch_bounds__(1024) k_oa() {
  const int re = blockIdx.x, tid = threadIdx.x;
  const float* F = g_frames + (size_t)re * 32 * 2048;
  float ss = 0.0f;
#pragma unroll
  for (int f = 0; f < 32; f++) {
    float v = F[f * 2048 + tid];
    if (f > 0) v += F[(f - 1) * 2048 + 1024 + tid];
    ss += v * v;
  }
#pragma unroll
  for (int o = 16; o > 0; o >>= 1) ss += __shfl_xor_sync(0xffffffffu, ss, o);
  __shared__ float red[32];
  if ((tid & 31) == 0) red[tid >> 5] = ss;
  __syncthreads();
  if (tid < 32) {
    float v = red[tid];
#pragma unroll
    for (int o = 16; o > 0; o >>= 1) v += __shfl_xor_sync(0xffffffffu, v, o);
    if (tid == 0) g_invnorm[re] = 1.0f / (sqrtf(v) + 1e-8f);
  }
}

// ---------------- K4: pass1 columns, signal (fused upsample*noise) ----------------
__global__ void __launch_bounds__(256) k_p1_sig() {
  __shared__ float2 tile[16 * 273];
  __shared__ float2 T16[256];
  __shared__ float rrow[128];
  const int tid = threadIdx.x;
  fill_T16(T16, tid);
  const int lane = tid >> 4, c = tid & 15;
  const int s = blockIdx.y;
  const int b = blockIdx.x * 16 + c;
  if (tid < 128) rrow[tid] = g_routed[s * 128 + tid];
  __syncthreads();
  float2 X[16];
#pragma unroll
  for (int n2 = 0; n2 < 16; n2++) {
    float v = 0.0f;
    if (n2 < 8) {
      int j = lane + 16 * n2;
      int n = b + 256 * j;
      float pos = fminf(fmaxf((n + 0.5f) * (1.0f / 256.0f) - 0.5f, 0.0f), 127.0f);
      int lo = (int)pos;
      int hi = min(lo + 1, 127);
      float w = pos - (float)lo;
      v = (rrow[lo] * (1.0f - w) + rrow[hi] * w) * noise_pm1((unsigned)(s * 32768 + n));
    }
    X[n2] = make_float2(v, 0.0f);
  }
  fft256g<-1, true>(X, lane, tile + c * 273, T16);
  float sv, cv;
  __sincosf(-(TWOPI_F / 65536.0f) * (float)(lane * b), &sv, &cv);
  float2 w0 = make_float2(cv, sv);
  __sincosf(-(TWOPI_F / 65536.0f) * (float)(16 * b), &sv, &cv);
  float2 s1 = make_float2(cv, sv);
  float2 cc[4];
  chain4(w0, s1, cc);
  __half2* dst = g_Fsig + (size_t)s * 65536 + b;
#pragma unroll
  for (int t = 0; t < 4; t++) {
#pragma unroll
    for (int j = 0; j < 4; j++) {
      int k2 = 4 * j + t;
      float2 z = cmul(X[k2], cc[j]);
      dst[(lane + 16 * k2) * 256] = __floats2half2_rn(z.x, z.y);
      cc[j] = cmul(cc[j], s1);
    }
  }
}

// ---------------- K5: pass1 columns, resonances (OLA + unit-norm inline) ----------------
__global__ void __launch_bounds__(256) k_p1_res() {
  __shared__ float2 tile[16 * 273];
  __shared__ float2 T16[256];
  const int tid = threadIdx.x;
  fill_T16(T16, tid);
  const int lane = tid >> 4, c = tid & 15;
  const int re = blockIdx.y;
  const int b = blockIdx.x * 16 + c;
  const float inv = g_invnorm[re];
  const float* F = g_frames + (size_t)re * 32 * 2048;
  float2 X[16];
#pragma unroll
  for (int n2 = 0; n2 < 16; n2++) {
    float v = 0.0f;
    if (n2 < 8) {
      int n = b + 256 * (lane + 16 * n2);
      int f = n >> 10, t = n & 1023;
      v = F[f * 2048 + t];
      if (f > 0) v += F[(f - 1) * 2048 + 1024 + t];
      v *= inv;
    }
    X[n2] = make_float2(v, 0.0f);
  }
  __syncthreads();   // T16 ready
  fft256g<-1, true>(X, lane, tile + c * 273, T16);
  float sv, cv;
  __sincosf(-(TWOPI_F / 65536.0f) * (float)(lane * b), &sv, &cv);
  float2 w0 = make_float2(cv, sv);
  __sincosf(-(TWOPI_F / 65536.0f) * (float)(16 * b), &sv, &cv);
  float2 s1 = make_float2(cv, sv);
  float2 cc[4];
  chain4(w0, s1, cc);
  float2* dst = g_Fres + (size_t)re * 65536 + b;
#pragma unroll
  for (int t = 0; t < 4; t++) {
#pragma unroll
    for (int j = 0; j < 4; j++) {
      int k2 = 4 * j + t;
      dst[(lane + 16 * k2) * 256] = cmul(X[k2], cc[j]);
      cc[j] = cmul(cc[j], s1);
    }
  }
}

// ---------------- K7: fused res-pass2 + fwd pass2(sig) + product + inverse pass1 ----------------
__global__ void __launch_bounds__(256) k_fused3() {
  __shared__ float2 tile[16 * 273];
  __shared__ float2 T16[256];
  const int tid = threadIdx.x;
  fill_T16(T16, tid);
  const int c = tid >> 4, lane = tid & 15;
  const int r = blockIdx.y;
  const int d = blockIdx.x * 16 + c;
  __syncthreads();   // T16 ready
  // --- inline res pass2 for this block's rows (thread-private RAW only) ---
#pragma unroll
  for (int re4 = 0; re4 < 4; re4++) {
    float2* row = g_Fres + (size_t)(r * 4 + re4) * 65536 + d * 256;
    float2 X[16];
#pragma unroll
    for (int n2 = 0; n2 < 16; n2++) X[n2] = row[lane + 16 * n2];
    fft256g<-1, false>(X, lane, tile + c * 273, T16);
#pragma unroll
    for (int k2 = 0; k2 < 16; k2++) row[lane + 16 * k2] = X[k2];
  }
  __syncwarp();
  for (int bc = 0; bc < 8; bc++) {
    const int s = bc * 32 + r;
    const __half2* srow = g_Fsig + (size_t)s * 65536 + d * 256;
    float2 X[16];
#pragma unroll
    for (int n2 = 0; n2 < 16; n2++) X[n2] = __half22float2(srow[lane + 16 * n2]);
    fft256g<-1, false>(X, lane, tile + c * 273, T16);
#pragma unroll
    for (int hb = 0; hb < 2; hb++) {
      const float2* f0 = g_Fres + (size_t)(r * 4 + 2 * hb) * 65536 + d * 256;
      const float2* f1 = f0 + 65536;
      float2 Y[16];
#pragma unroll
      for (int k = 0; k < 16; k++) {
        int e = lane + 16 * k;
        float2 a = X[k];
        float2 p0 = cmul(a, f0[e]);
        float2 p1 = cmul(a, f1[e]);
        Y[k] = make_float2(p0.x - p1.y, p0.y + p1.x);   // p0 + i*p1
      }
      fft256g<1, false>(Y, lane, tile + c * 273, T16);
      float sv, cv;
      __sincosf((TWOPI_F / 65536.0f) * (float)(lane * d), &sv, &cv);
      const float scl = 1.0f / 65536.0f;
      float2 w0 = make_float2(cv * scl, sv * scl);
      __sincosf((TWOPI_F / 65536.0f) * (float)(16 * d), &sv, &cv);
      float2 s1 = make_float2(cv, sv);
      float2 cc[4];
      chain4(w0, s1, cc);
      float2* st = tile + c * 273;
      __syncwarp();
#pragma unroll
      for (int t = 0; t < 4; t++) {
#pragma unroll
        for (int j = 0; j < 4; j++) {
          int k2 = 4 * j + t;
          st[lane + 16 * k2] = cmul(Y[k2], cc[j]);
          cc[j] = cmul(cc[j], s1);
        }
      }
      __syncthreads();
      const int oc = tid & 15, jb = tid >> 4;
      __half2* dst = g_B + ((size_t)(s * 2 + hb)) * 65536 + blockIdx.x * 16 + oc;
      const float2* sr2 = tile + oc * 273;
#pragma unroll
      for (int m = 0; m < 16; m++) {
        float2 z = sr2[jb + 16 * m];
        dst[(jb + 16 * m) * 256] = __floats2half2_rn(z.x, z.y);
      }
      __syncthreads();
    }
  }
}

// ---------------- K8: fused inverse pass2 + deformation mix + tanh (partial r-sum) ----------------
__global__ void __launch_bounds__(256) k_invfinal(const float* __restrict__ gains) {
  __shared__ float2 tile[16 * 273];
  __shared__ float2 T16[256];
  __shared__ float dw[512];
  __shared__ float ga[32];
  const int tid = threadIdx.x;
  fill_T16(T16, tid);
  const int c = tid >> 4, lane = tid & 15;
  const int bc = blockIdx.y, rz = blockIdx.z;
  const int bp = blockIdx.x * 16 + c;
  for (int i = tid; i < 512; i += 256) dw[i] = g_dw[bc * 512 + i];
  if (tid < 32) ga[tid] = fabsf(gains[tid]);
  __syncthreads();
  float d0[8], d1[8], d2[8], d3[8], accv[8];
#pragma unroll
  for (int k2 = 0; k2 < 8; k2++) {
    int n = bp + 256 * (lane + 16 * k2);
    float pos = fminf(fmaxf((n + 0.5f) * (1.0f / 256.0f) - 0.5f, 0.0f), 127.0f);
    int lo = (int)pos;
    int hi = min(lo + 1, 127);
    float w = pos - (float)lo;
    d0[k2] = dw[lo]       * (1.0f - w) + dw[hi]       * w;
    d1[k2] = dw[128 + lo] * (1.0f - w) + dw[128 + hi] * w;
    d2[k2] = dw[256 + lo] * (1.0f - w) + dw[256 + hi] * w;
    d3[k2] = dw[384 + lo] * (1.0f - w) + dw[384 + hi] * w;
    accv[k2] = 0.0f;
  }
  for (int rr = 0; rr < 8; rr++) {
    const int r = rz * 8 + rr;
    const size_t base = ((size_t)((bc * 32 + r) * 2)) * 65536 + (size_t)bp * 256;
    float2 Y0[8];
    {
      const __half2* row = g_B + base;
      float2 X[16];
#pragma unroll
      for (int n2 = 0; n2 < 16; n2++) X[n2] = __half22float2(row[lane + 16 * n2]);
      fft256g<1, false>(X, lane, tile + c * 273, T16);
#pragma unroll
      for (int k2 = 0; k2 < 8; k2++) Y0[k2] = X[k2];
    }
    float2 X[16];
    {
      const __half2* row = g_B + base + 65536;
#pragma unroll
      for (int n2 = 0; n2 < 16; n2++) X[n2] = __half22float2(row[lane + 16 * n2]);
      fft256g<1, false>(X, lane, tile + c * 273, T16);
    }
    const float gn = ga[r];
#pragma unroll
    for (int k2 = 0; k2 < 8; k2++) {
      float sx = d0[k2] * Y0[k2].x + d1[k2] * Y0[k2].y + d2[k2] * X[k2].x + d3[k2] * X[k2].y;
      sx = fminf(fmaxf(sx * gn, -15.0f), 15.0f);
      float z = __expf(2.0f * sx);
      accv[k2] += __fdividef(z - 1.0f, z + 1.0f);
    }
  }
  float* dst = g_part + (size_t)rz * 262144 + bc * 32768;
#pragma unroll
  for (int k2 = 0; k2 < 8; k2++) {
    int n = bp + 256 * (lane + 16 * k2);
    dst[n] = accv[k2];
  }
}

// ---------------- K9: reduce 4 partials into output ----------------
__global__ void __launch_bounds__(256) k_reduce(float* __restrict__ out) {
  int i = blockIdx.x * 256 + threadIdx.x;  // 262144
  out[i] = g_part[i] + g_part[262144 + i] + g_part[524288 + i] + g_part[786432 + i];
}

extern "C" void kernel_launch(void* const* d_in, const int* in_sizes, int n_in,
                              void* d_out, int out_size) {
  const float* cs     = (const float*)d_in[0];
  const float* defs   = (const float*)d_in[1];
  const float* router = (const float*)d_in[2];
  const float* amp    = (const float*)d_in[3];
  const float* phase  = (const float*)d_in[4];
  const float* decay  = (const float*)d_in[5];
  const float* gains  = (const float*)d_in[6];
  float* out = (float*)d_out;

  // k_p1_sig moved to the 4th launch slot: the ncu capture window has
  // consistently profiled launch #4 (k_frames* in R2-R6), so this round it
  // should capture k_p1_sig and size the threefry cost directly.
  k_routed<<<128, 256>>>(cs, router, out);
  k_dw<<<4, 256>>>(defs);
  k_spec0<<<dim3(5, 128), 256>>>(amp, phase, decay);
  k_p1_sig<<<dim3(16, 256), 256>>>();
  k_frames2<<<dim3(8, 128), 256>>>();
  k_oa<<<128, 1024>>>();
  k_p1_res<<<dim3(16, 128), 256>>>();
  k_fused3<<<dim3(16, 32), 256>>>();
  k_invfinal<<<dim3(16, 8, 4), 256>>>(gains);
  k_reduce<<<1024, 256>>>(out);
}